// round 7
// baseline (speedup 1.0000x reference)
#include <cuda_runtime.h>

#define TPB 256
#define NWARP 8
#define NLOC 48        // locations (output columns) per block = half row
#define LOCW 6         // locations per warp in GEMM phases

#define ROW_S 51       // row stride in sh_x (50 cols + 1 pad, odd -> conflict-free)
#define CH_S  153      // channel stride = 3*ROW_S

// Pre-transposed alpha_w: g_awT[h*64 + c2] = alpha_w[c2*64 + h]
__device__ float g_awT[64 * 64];

__global__ void prep_transpose(const float* __restrict__ aw) {
    int i = blockIdx.x * blockDim.x + threadIdx.x;
    if (i < 4096) {
        int hh = i >> 6, c2 = i & 63;
        g_awT[i] = aw[c2 * 64 + hh];
    }
}

// Shared layout (floats), 8192 total = 32 KB:
//   [0    .. 4896)  sh_x   : 32 ch * 3 rows * 51   (aliased as sh_out 48*65 later)
//   [4896 .. 7968)  sh_h   : 48 loc * 64 hidden
//   [7968 .. 8016)  sh_proj: 48
//   [8016 .. 8064)  sh_pb  : 48
//   [8064 .. 8192)  sh_hist: 8 warps * 16 bins (int)
#define SMEM_FLOATS 8192
#define SMEM_BYTES  (SMEM_FLOATS * 4)

__global__ __launch_bounds__(TPB, 4)
void sac_kernel(const float* __restrict__ x,
                const float* __restrict__ fc1_w, const float* __restrict__ fc1_b,
                const float* __restrict__ alpha_b,
                const float* __restrict__ phi_w, const float* __restrict__ phi_b,
                const float* __restrict__ bn_gamma, const float* __restrict__ bn_beta,
                const float* __restrict__ bn_mean, const float* __restrict__ bn_var,
                float* __restrict__ out)
{
    extern __shared__ float smem[];
    float* sh_x    = smem;
    float* sh_h    = smem + 4896;
    float* sh_proj = smem + 7968;
    float* sh_pb   = smem + 8016;
    int*   sh_hist = (int*)(smem + 8064);
    float* sh_out  = smem;   // aliases sh_x after phase 2 (guarded by __syncthreads)

    const int y    = blockIdx.x >> 1;        // output row 0..95
    const int half = blockIdx.x & 1;         // half-row 0..1 (cols half*48 .. half*48+47)
    const int b    = blockIdx.y;             // batch 0..3
    const int tid  = threadIdx.x;
    const int warp = tid >> 5;
    const int lane = tid & 31;

    // ---------------- phase 0: stage x rows (y-1,y,y+1), cols half*48-1 .. half*48+48 ----
    const float* xb = x + (size_t)b * 32 * 9216;
    const int gx0 = half * 48 - 1;
    for (int i = tid; i < 32 * 3 * 50; i += TPB) {
        int c   = i / 150;
        int rem = i - c * 150;
        int r   = rem / 50;
        int cc  = rem - r * 50;
        int gy  = y + r - 1;
        int gx  = gx0 + cc;
        float v = 0.f;
        if ((unsigned)gy < 96u && (unsigned)gx < 96u)
            v = xb[(c * 96 + gy) * 96 + gx];
        sh_x[c * CH_S + r * ROW_S + cc] = v;
    }
    __syncthreads();

    // ---------------- phase 1: stats + fc1 hidden, warp-per-location (6 iters) ----------
    const float inv288 = 1.0f / 288.0f;
    const float invPr  = 1.0f / (288.0f + 1e-6f);

    float pbw[9];
    #pragma unroll
    for (int k = 0; k < 9; k++) pbw[k] = __ldg(&phi_b[lane * 9 + k]);
    float w1c[5], w1c2[5];
    #pragma unroll
    for (int k = 0; k < 5; k++) {
        w1c[k]  = __ldg(&fc1_w[lane * 5 + k]);
        w1c2[k] = __ldg(&fc1_w[(lane + 32) * 5 + k]);
    }
    const float b1  = __ldg(&fc1_b[lane]);
    const float b1b = __ldg(&fc1_b[lane + 32]);

    for (int li = warp; li < NLOC; li += NWARP) {
        float v[9];
        const float* base = sh_x + lane * CH_S + li;
        #pragma unroll
        for (int r = 0; r < 3; r++)
            #pragma unroll
            for (int kc = 0; kc < 3; kc++)
                v[r * 3 + kc] = base[r * ROW_S + kc];

        // single pass: raw moments + min/max + phi_b dot
        float S1 = 0.f, S2 = 0.f, S3 = 0.f, S4 = 0.f, pbp = 0.f;
        float mn = v[0], mx = v[0];
        #pragma unroll
        for (int k = 0; k < 9; k++) {
            float vk = v[k];
            float v2 = vk * vk;
            S1 += vk; S2 += v2; S3 += v2 * vk; S4 += v2 * v2;
            mn = fminf(mn, vk);
            mx = fmaxf(mx, vk);
            pbp += pbw[k] * vk;
        }
        #pragma unroll
        for (int o = 16; o; o >>= 1) {
            S1  += __shfl_xor_sync(0xffffffffu, S1,  o);
            S2  += __shfl_xor_sync(0xffffffffu, S2,  o);
            S3  += __shfl_xor_sync(0xffffffffu, S3,  o);
            S4  += __shfl_xor_sync(0xffffffffu, S4,  o);
            pbp += __shfl_xor_sync(0xffffffffu, pbp, o);
            mn = fminf(mn, __shfl_xor_sync(0xffffffffu, mn, o));
            mx = fmaxf(mx, __shfl_xor_sync(0xffffffffu, mx, o));
        }
        float mu = S1 * inv288;
        float r2 = S2 * inv288, r3 = S3 * inv288, r4 = S4 * inv288;
        float mu2 = mu * mu;
        float m2 = r2 - mu2;
        float m3 = r3 - mu * (3.0f * r2 - 2.0f * mu2);
        float m4 = r4 - mu * (4.0f * r3 - mu * (6.0f * r2 - 3.0f * mu2));
        float sigma = sqrtf(m2 + 1e-6f);
        float q   = sigma + 1e-6f;
        float iq  = 1.0f / q;
        float iq2 = iq * iq;
        float gam = m3 * iq2 * iq;
        float kap = m4 * iq2 * iq2 - 3.0f;

        // histogram entropy (binning bit-matches reference)
        int* hist = sh_hist + warp * 16;
        if (lane < 16) hist[lane] = 0;
        __syncwarp();
        float denom = (mx - mn) + 1e-6f;
        #pragma unroll
        for (int k = 0; k < 9; k++) {
            float pn = (v[k] - mn) / denom;
            int bi = (int)(pn * 15.0f);
            bi = max(0, min(15, bi));
            atomicAdd(&hist[bi], 1);
        }
        __syncwarp();
        float ent = 0.f;
        if (lane < 16) {
            float prob = (float)hist[lane] * invPr;
            ent = -prob * logf(prob + 1e-9f);
        }
        __syncwarp();
        #pragma unroll
        for (int o = 16; o; o >>= 1)
            ent += __shfl_xor_sync(0xffffffffu, ent, o);

        // fc1 + relu
        float ss[5] = {mu, sigma, gam, kap, ent};
        float h0 = b1, h1 = b1b;
        #pragma unroll
        for (int k = 0; k < 5; k++) {
            h0 += w1c[k]  * ss[k];
            h1 += w1c2[k] * ss[k];
        }
        sh_h[li * 64 + lane]      = fmaxf(h0, 0.f);
        sh_h[li * 64 + lane + 32] = fmaxf(h1, 0.f);
        if (lane == 0) sh_pb[li] = pbp;
    }
    __syncthreads();

    // ---------------- phase 2: phi GEMM (t = phi_w^T @ patch) + proj ----------------
    // lane = h-pair (h=2*lane, 2*lane+1); warp covers 6 locations x0..x0+5
    const int x0 = warp * LOCW;
    float acc0[LOCW], acc1[LOCW];
    #pragma unroll
    for (int l = 0; l < LOCW; l++) { acc0[l] = 0.f; acc1[l] = 0.f; }

    const float2* pw = (const float2*)phi_w;   // phi_w[j*64 + h], float2 idx = j*32 + lane
    for (int c = 0; c < 32; c++) {
        #pragma unroll
        for (int kh = 0; kh < 3; kh++) {
            const float* rp = sh_x + c * CH_S + kh * ROW_S + x0;
            float p[LOCW + 2];
            #pragma unroll
            for (int t = 0; t < LOCW + 2; t++) p[t] = rp[t];   // uniform broadcasts
            int jb = c * 9 + kh * 3;
            #pragma unroll
            for (int kw = 0; kw < 3; kw++) {
                float2 w = __ldg(&pw[(jb + kw) * 32 + lane]);
                #pragma unroll
                for (int l = 0; l < LOCW; l++) {
                    acc0[l] += w.x * p[l + kw];
                    acc1[l] += w.y * p[l + kw];
                }
            }
        }
    }
    // proj[l] = sum_h h[l][h] * t[h][l]  (+ phi_b . patch)
    float pr[LOCW];
    #pragma unroll
    for (int l = 0; l < LOCW; l++) {
        float2 hv = ((const float2*)(sh_h + (x0 + l) * 64))[lane];
        pr[l] = acc0[l] * hv.x + acc1[l] * hv.y;
    }
    #pragma unroll
    for (int o = 16; o; o >>= 1)
        #pragma unroll
        for (int l = 0; l < LOCW; l++)
            pr[l] += __shfl_xor_sync(0xffffffffu, pr[l], o);
    if (lane == 0) {
        #pragma unroll
        for (int l = 0; l < LOCW; l++)
            sh_proj[x0 + l] = pr[l] + sh_pb[x0 + l];
    }
    __syncthreads();   // retires all sh_x reads before sh_out alias writes

    // ---------------- phase 3: alpha GEMM + BN + SiLU -> sh_out (transpose buffer) ----
    const int c20 = 2 * lane;
    float a0[LOCW], a1[LOCW];
    {
        float ab0 = __ldg(&alpha_b[c20]), ab1 = __ldg(&alpha_b[c20 + 1]);
        #pragma unroll
        for (int l = 0; l < LOCW; l++) { a0[l] = ab0; a1[l] = ab1; }
    }
    const float2* awT = (const float2*)g_awT;  // awT[h*64 + c2]
    for (int hh = 0; hh < 64; hh += 4) {
        float2 w0 = __ldg(&awT[(hh + 0) * 32 + lane]);
        float2 w1 = __ldg(&awT[(hh + 1) * 32 + lane]);
        float2 w2 = __ldg(&awT[(hh + 2) * 32 + lane]);
        float2 w3 = __ldg(&awT[(hh + 3) * 32 + lane]);
        #pragma unroll
        for (int l = 0; l < LOCW; l++) {
            const float4 hv = *(const float4*)(sh_h + (x0 + l) * 64 + hh);
            a0[l] += w0.x * hv.x + w1.x * hv.y + w2.x * hv.z + w3.x * hv.w;
            a1[l] += w0.y * hv.x + w1.y * hv.y + w2.y * hv.z + w3.y * hv.w;
        }
    }
    {
        float inv0 = __ldg(&bn_gamma[c20])     / sqrtf(__ldg(&bn_var[c20])     + 1e-5f);
        float inv1 = __ldg(&bn_gamma[c20 + 1]) / sqrtf(__ldg(&bn_var[c20 + 1]) + 1e-5f);
        float m0 = __ldg(&bn_mean[c20]), m1 = __ldg(&bn_mean[c20 + 1]);
        float be0 = __ldg(&bn_beta[c20]), be1 = __ldg(&bn_beta[c20 + 1]);
        #pragma unroll
        for (int l = 0; l < LOCW; l++) {
            float pj = sh_proj[x0 + l];
            float y0 = (a0[l] * pj - m0) * inv0 + be0;
            float y1 = (a1[l] * pj - m1) * inv1 + be1;
            sh_out[(x0 + l) * 65 + c20]     = y0 / (1.0f + __expf(-y0));
            sh_out[(x0 + l) * 65 + c20 + 1] = y1 / (1.0f + __expf(-y1));
        }
    }
    __syncthreads();

    // ---------------- phase 4: coalesced global write (48 cols x 64 ch) ----------------
    float* ob = out + (size_t)b * 64 * 9216 + y * 96 + half * 48;
    for (int i = tid; i < 64 * NLOC; i += TPB) {
        int c2 = i / NLOC;
        int xx = i - c2 * NLOC;
        ob[(size_t)c2 * 9216 + xx] = sh_out[xx * 65 + c2];
    }
}

extern "C" void kernel_launch(void* const* d_in, const int* in_sizes, int n_in,
                              void* d_out, int out_size) {
    // ---- Resolve inputs by SIZE (robust to metadata ordering), with positional fallback ----
    int ix = -1, ifc1w = -1, iaw = -1, ipw = -1, ipb = -1;
    int idx64[8]; int n64 = 0;
    for (int i = 0; i < n_in; i++) {
        switch (in_sizes[i]) {
            case 1179648: ix    = i; break;
            case 18432:   ipw   = i; break;
            case 4096:    iaw   = i; break;
            case 320:     ifc1w = i; break;
            case 288:     ipb   = i; break;
            case 64:      if (n64 < 8) idx64[n64++] = i; break;
            default: break;
        }
    }
    int ifc1b, iab, ibg, ibb, ibm, ibv;
    if (ix < 0 || ipw < 0 || iaw < 0 || ifc1w < 0 || ipb < 0 || n64 < 6) {
        ix = 0; ifc1w = 1; ifc1b = 2; iaw = 3; iab = 4; ipw = 5; ipb = 6;
        ibg = 7; ibb = 8; ibm = 9; ibv = 10;
    } else if (ix == 0) {
        ifc1b = idx64[0]; iab = idx64[1]; ibg = idx64[2];
        ibb   = idx64[3]; ibm = idx64[4]; ibv = idx64[5];
    } else {
        iab   = idx64[0]; ibb = idx64[1]; ibg = idx64[2];
        ibm   = idx64[3]; ibv = idx64[4]; ifc1b = idx64[5];
    }

    const float* x        = (const float*)d_in[ix];
    const float* fc1_w    = (const float*)d_in[ifc1w];
    const float* fc1_b    = (const float*)d_in[ifc1b];
    const float* alpha_w  = (const float*)d_in[iaw];
    const float* alpha_b  = (const float*)d_in[iab];
    const float* phi_w    = (const float*)d_in[ipw];
    const float* phi_b    = (const float*)d_in[ipb];
    const float* bn_gamma = (const float*)d_in[ibg];
    const float* bn_beta  = (const float*)d_in[ibb];
    const float* bn_mean  = (const float*)d_in[ibm];
    const float* bn_var   = (const float*)d_in[ibv];
    float* out = (float*)d_out;

    prep_transpose<<<16, 256>>>(alpha_w);
    dim3 grid(192, 4);   // (row*2 + half, batch)
    sac_kernel<<<grid, TPB, SMEM_BYTES>>>(x, fc1_w, fc1_b, alpha_b, phi_w, phi_b,
                                          bn_gamma, bn_beta, bn_mean, bn_var, out);
}

// round 8
// speedup vs baseline: 1.0355x; 1.0355x over previous
#include <cuda_runtime.h>

#define TPB 256
#define NWARP 8
#define LOCW 12

// Pre-transposed alpha_w: g_awT[h*64 + c2] = alpha_w[c2*64 + h]
__device__ float g_awT[64 * 64];

__global__ void prep_transpose(const float* __restrict__ aw) {
    int i = blockIdx.x * blockDim.x + threadIdx.x;
    if (i < 4096) {
        int hh = i >> 6, c2 = i & 63;
        g_awT[i] = aw[c2 * 64 + hh];
    }
}

// Shared layout (floats):
//   [0      .. 9504)  sh_x   : 32 ch * (3 rows * 99 cols), stride 297 (odd -> conflict-free)
//                              aliased as sh_out (96*65) after phase 2
//   [9504   .. 15648) sh_h   : 96 locations * 64 hidden
//   [15648  .. 15744) sh_proj: 96
//   [15744  .. 15840) sh_pb  : 96  (phi_b . patch term)
#define SMEM_FLOATS 15840
#define SMEM_BYTES  (SMEM_FLOATS * 4)

__global__ __launch_bounds__(TPB, 3)
void sac_kernel(const float* __restrict__ x,
                const float* __restrict__ fc1_w, const float* __restrict__ fc1_b,
                const float* __restrict__ alpha_b,
                const float* __restrict__ phi_w, const float* __restrict__ phi_b,
                const float* __restrict__ bn_gamma, const float* __restrict__ bn_beta,
                const float* __restrict__ bn_mean, const float* __restrict__ bn_var,
                float* __restrict__ out)
{
    extern __shared__ float smem[];
    float* sh_x    = smem;
    float* sh_h    = smem + 9504;
    float* sh_proj = smem + 15648;
    float* sh_pb   = smem + 15744;
    float* sh_out  = smem;   // aliases sh_x after phase 2 (guarded by __syncthreads)

    const int y    = blockIdx.x;   // output row 0..95
    const int b    = blockIdx.y;   // batch 0..3
    const int tid  = threadIdx.x;
    const int warp = tid >> 5;
    const int lane = tid & 31;

    // ---------------- phase 0: stage x rows (y-1, y, y+1), zero padded ----------------
    const float* xb = x + (size_t)b * 32 * 9216;
    for (int i = tid; i < 32 * 3 * 98; i += TPB) {
        int c   = i / 294;
        int rem = i - c * 294;
        int r   = rem / 98;
        int cc  = rem - r * 98;          // cc corresponds to gx = cc-1
        int gy  = y + r - 1;
        int gx  = cc - 1;
        float v = 0.f;
        if ((unsigned)gy < 96u && (unsigned)gx < 96u)
            v = xb[(c * 96 + gy) * 96 + gx];
        sh_x[c * 297 + r * 99 + cc] = v;
    }
    __syncthreads();

    // ---------------- phase 1: stats + fc1 hidden, warp-per-location ----------------
    const float inv288 = 1.0f / 288.0f;
    const float invPr  = 1.0f / (288.0f + 1e-6f);   // reference: counts / (ckk + 1e-6)

    // lane-invariant weights hoisted out of the li loop
    float pbw[9];
    #pragma unroll
    for (int k = 0; k < 9; k++) pbw[k] = __ldg(&phi_b[lane * 9 + k]);
    float w1c[5], w1c2[5];
    #pragma unroll
    for (int k = 0; k < 5; k++) {
        w1c[k]  = __ldg(&fc1_w[lane * 5 + k]);
        w1c2[k] = __ldg(&fc1_w[(lane + 32) * 5 + k]);
    }
    const float b1  = __ldg(&fc1_b[lane]);
    const float b1b = __ldg(&fc1_b[lane + 32]);

    for (int li = warp; li < 96; li += NWARP) {
        // lane = channel; 3x3 taps
        float v[9];
        const float* base = sh_x + lane * 297 + li;
        #pragma unroll
        for (int r = 0; r < 3; r++)
            #pragma unroll
            for (int kc = 0; kc < 3; kc++)
                v[r * 3 + kc] = base[r * 99 + kc];

        // single pass: raw moments + min/max + phi_b dot
        float S1 = 0.f, S2 = 0.f, S3 = 0.f, S4 = 0.f, pbp = 0.f;
        float mn = v[0], mx = v[0];
        #pragma unroll
        for (int k = 0; k < 9; k++) {
            float vk = v[k];
            float v2 = vk * vk;
            S1 += vk; S2 += v2; S3 += v2 * vk; S4 += v2 * v2;
            mn = fminf(mn, vk);
            mx = fmaxf(mx, vk);
            pbp += pbw[k] * vk;
        }
        // one 7-value butterfly reduction
        #pragma unroll
        for (int o = 16; o; o >>= 1) {
            S1  += __shfl_xor_sync(0xffffffffu, S1,  o);
            S2  += __shfl_xor_sync(0xffffffffu, S2,  o);
            S3  += __shfl_xor_sync(0xffffffffu, S3,  o);
            S4  += __shfl_xor_sync(0xffffffffu, S4,  o);
            pbp += __shfl_xor_sync(0xffffffffu, pbp, o);
            mn = fminf(mn, __shfl_xor_sync(0xffffffffu, mn, o));
            mx = fmaxf(mx, __shfl_xor_sync(0xffffffffu, mx, o));
        }
        float mu = S1 * inv288;
        float r2 = S2 * inv288, r3 = S3 * inv288, r4 = S4 * inv288;
        float mu2 = mu * mu;
        float m2 = r2 - mu2;
        float m3 = r3 - mu * (3.0f * r2 - 2.0f * mu2);
        float m4 = r4 - mu * (4.0f * r3 - mu * (6.0f * r2 - 3.0f * mu2));
        float sigma = sqrtf(m2 + 1e-6f);
        float q   = sigma + 1e-6f;
        float iq  = 1.0f / q;
        float iq2 = iq * iq;
        float gam = m3 * iq2 * iq;
        float kap = m4 * iq2 * iq2 - 3.0f;

        // ---- register SIMD histogram (no atomics, no smem, no syncwarp) ----
        // per-lane: 16 nibble counters in one u64 (max 9 per nibble)
        unsigned long long nib = 0ULL;
        float denom = (mx - mn) + 1e-6f;
        #pragma unroll
        for (int k = 0; k < 9; k++) {
            float pn = (v[k] - mn) / denom;    // IEEE div, matches reference
            int bi = (int)(pn * 15.0f);        // truncation == astype(int32)
            bi = max(0, min(15, bi));
            nib += 1ULL << (bi * 4);
        }
        // nibbles -> packed bytes: A = even bins {0,2,..,14}, Bp = odd bins {1,3,..,15}
        unsigned long long A  =  nib       & 0x0F0F0F0F0F0F0F0FULL;
        unsigned long long Bp = (nib >> 4) & 0x0F0F0F0F0F0F0F0FULL;
        // 4 butterfly rounds in bytes (per-byte max 9*16=144 < 256, no carry)
        #pragma unroll
        for (int o = 1; o <= 8; o <<= 1) {
            A  += __shfl_xor_sync(0xffffffffu, A,  o);
            Bp += __shfl_xor_sync(0xffffffffu, Bp, o);
        }
        // bytes -> halfwords for the final round (max 288 < 65536)
        unsigned long long A0 =  A        & 0x00FF00FF00FF00FFULL;  // bins 4p
        unsigned long long A1 = (A  >> 8) & 0x00FF00FF00FF00FFULL;  // bins 4p+2
        unsigned long long B0 =  Bp       & 0x00FF00FF00FF00FFULL;  // bins 4p+1
        unsigned long long B1 = (Bp >> 8) & 0x00FF00FF00FF00FFULL;  // bins 4p+3
        A0 += __shfl_xor_sync(0xffffffffu, A0, 16);
        A1 += __shfl_xor_sync(0xffffffffu, A1, 16);
        B0 += __shfl_xor_sync(0xffffffffu, B0, 16);
        B1 += __shfl_xor_sync(0xffffffffu, B1, 16);

        float ent = 0.f;
        if (lane < 16) {
            unsigned long long w = (lane & 1) ? ((lane & 2) ? B1 : B0)
                                              : ((lane & 2) ? A1 : A0);
            unsigned cnt = (unsigned)(w >> ((lane >> 2) * 16)) & 0xFFFFu;
            float prob = (float)cnt * invPr;
            ent = -prob * logf(prob + 1e-9f);
        }
        #pragma unroll
        for (int o = 16; o; o >>= 1)
            ent += __shfl_xor_sync(0xffffffffu, ent, o);

        // fc1 + relu; lane computes h[lane] and h[lane+32]
        float ss[5] = {mu, sigma, gam, kap, ent};
        float h0 = b1, h1 = b1b;
        #pragma unroll
        for (int k = 0; k < 5; k++) {
            h0 += w1c[k]  * ss[k];
            h1 += w1c2[k] * ss[k];
        }
        sh_h[li * 64 + lane]      = fmaxf(h0, 0.f);
        sh_h[li * 64 + lane + 32] = fmaxf(h1, 0.f);
        if (lane == 0) sh_pb[li] = pbp;
    }
    __syncthreads();

    // ---------------- phase 2: phi GEMM (t = phi_w^T @ patch) + proj ----------------
    // lane = h-pair (h = 2*lane, 2*lane+1); warp covers 12 locations x0..x0+11
    const int x0 = warp * LOCW;
    float acc0[LOCW], acc1[LOCW];
    #pragma unroll
    for (int l = 0; l < LOCW; l++) { acc0[l] = 0.f; acc1[l] = 0.f; }

    const float2* pw = (const float2*)phi_w;   // phi_w[j*64 + h], float2 idx = j*32 + lane
    for (int c = 0; c < 32; c++) {
        #pragma unroll
        for (int kh = 0; kh < 3; kh++) {
            const float* rp = sh_x + c * 297 + kh * 99 + x0;
            float p[LOCW + 2];
            #pragma unroll
            for (int t = 0; t < LOCW + 2; t++) p[t] = rp[t];   // uniform broadcasts
            int jb = c * 9 + kh * 3;
            #pragma unroll
            for (int kw = 0; kw < 3; kw++) {
                float2 w = __ldg(&pw[(jb + kw) * 32 + lane]);
                #pragma unroll
                for (int l = 0; l < LOCW; l++) {
                    acc0[l] += w.x * p[l + kw];
                    acc1[l] += w.y * p[l + kw];
                }
            }
        }
    }
    // proj[l] = sum_h h[l][h] * t[h][l]  (+ phi_b . patch)
    float pr[LOCW];
    #pragma unroll
    for (int l = 0; l < LOCW; l++) {
        float2 hv = ((const float2*)(sh_h + (x0 + l) * 64))[lane];
        pr[l] = acc0[l] * hv.x + acc1[l] * hv.y;
    }
    #pragma unroll
    for (int o = 16; o; o >>= 1)
        #pragma unroll
        for (int l = 0; l < LOCW; l++)
            pr[l] += __shfl_xor_sync(0xffffffffu, pr[l], o);
    if (lane == 0) {
        #pragma unroll
        for (int l = 0; l < LOCW; l++)
            sh_proj[x0 + l] = pr[l] + sh_pb[x0 + l];
    }
    __syncthreads();   // retires all sh_x reads before sh_out alias writes

    // ---------------- phase 3: alpha GEMM + BN + SiLU -> sh_out (transpose buffer) ----
    const int c20 = 2 * lane;
    float a0[LOCW], a1[LOCW];
    {
        float ab0 = __ldg(&alpha_b[c20]), ab1 = __ldg(&alpha_b[c20 + 1]);
        #pragma unroll
        for (int l = 0; l < LOCW; l++) { a0[l] = ab0; a1[l] = ab1; }
    }
    const float2* awT = (const float2*)g_awT;  // awT[h*64 + c2]
    for (int hh = 0; hh < 64; hh += 4) {
        float2 w0 = __ldg(&awT[(hh + 0) * 32 + lane]);
        float2 w1 = __ldg(&awT[(hh + 1) * 32 + lane]);
        float2 w2 = __ldg(&awT[(hh + 2) * 32 + lane]);
        float2 w3 = __ldg(&awT[(hh + 3) * 32 + lane]);
        #pragma unroll
        for (int l = 0; l < LOCW; l++) {
            const float4 hv = *(const float4*)(sh_h + (x0 + l) * 64 + hh);
            a0[l] += w0.x * hv.x + w1.x * hv.y + w2.x * hv.z + w3.x * hv.w;
            a1[l] += w0.y * hv.x + w1.y * hv.y + w2.y * hv.z + w3.y * hv.w;
        }
    }
    {
        float inv0 = __ldg(&bn_gamma[c20])     / sqrtf(__ldg(&bn_var[c20])     + 1e-5f);
        float inv1 = __ldg(&bn_gamma[c20 + 1]) / sqrtf(__ldg(&bn_var[c20 + 1]) + 1e-5f);
        float m0 = __ldg(&bn_mean[c20]), m1 = __ldg(&bn_mean[c20 + 1]);
        float be0 = __ldg(&bn_beta[c20]), be1 = __ldg(&bn_beta[c20 + 1]);
        #pragma unroll
        for (int l = 0; l < LOCW; l++) {
            float pj = sh_proj[x0 + l];
            float y0 = (a0[l] * pj - m0) * inv0 + be0;
            float y1 = (a1[l] * pj - m1) * inv1 + be1;
            sh_out[(x0 + l) * 65 + c20]     = y0 / (1.0f + __expf(-y0));
            sh_out[(x0 + l) * 65 + c20 + 1] = y1 / (1.0f + __expf(-y1));
        }
    }
    __syncthreads();

    // ---------------- phase 4: coalesced global write ----------------
    float* ob = out + (size_t)b * 64 * 9216 + y * 96;
    for (int i = tid; i < 6144; i += TPB) {
        int c2 = i / 96;
        int xx = i - c2 * 96;
        ob[(size_t)c2 * 9216 + xx] = sh_out[xx * 65 + c2];
    }
}

extern "C" void kernel_launch(void* const* d_in, const int* in_sizes, int n_in,
                              void* d_out, int out_size) {
    // ---- Resolve inputs by SIZE (robust to metadata ordering), with positional fallback ----
    int ix = -1, ifc1w = -1, iaw = -1, ipw = -1, ipb = -1;
    int idx64[8]; int n64 = 0;
    for (int i = 0; i < n_in; i++) {
        switch (in_sizes[i]) {
            case 1179648: ix    = i; break;
            case 18432:   ipw   = i; break;
            case 4096:    iaw   = i; break;
            case 320:     ifc1w = i; break;
            case 288:     ipb   = i; break;
            case 64:      if (n64 < 8) idx64[n64++] = i; break;
            default: break;
        }
    }
    int ifc1b, iab, ibg, ibb, ibm, ibv;
    if (ix < 0 || ipw < 0 || iaw < 0 || ifc1w < 0 || ipb < 0 || n64 < 6) {
        ix = 0; ifc1w = 1; ifc1b = 2; iaw = 3; iab = 4; ipw = 5; ipb = 6;
        ibg = 7; ibb = 8; ibm = 9; ibv = 10;
    } else if (ix == 0) {
        ifc1b = idx64[0]; iab = idx64[1]; ibg = idx64[2];
        ibb   = idx64[3]; ibm = idx64[4]; ibv = idx64[5];
    } else {
        iab   = idx64[0]; ibb = idx64[1]; ibg = idx64[2];
        ibm   = idx64[3]; ibv = idx64[4]; ifc1b = idx64[5];
    }

    const float* x        = (const float*)d_in[ix];
    const float* fc1_w    = (const float*)d_in[ifc1w];
    const float* fc1_b    = (const float*)d_in[ifc1b];
    const float* alpha_w  = (const float*)d_in[iaw];
    const float* alpha_b  = (const float*)d_in[iab];
    const float* phi_w    = (const float*)d_in[ipw];
    const float* phi_b    = (const float*)d_in[ipb];
    const float* bn_gamma = (const float*)d_in[ibg];
    const float* bn_beta  = (const float*)d_in[ibb];
    const float* bn_mean  = (const float*)d_in[ibm];
    const float* bn_var   = (const float*)d_in[ibv];
    float* out = (float*)d_out;

    cudaFuncSetAttribute(sac_kernel, cudaFuncAttributeMaxDynamicSharedMemorySize, SMEM_BYTES);

    prep_transpose<<<16, 256>>>(alpha_w);
    dim3 grid(96, 4);
    sac_kernel<<<grid, TPB, SMEM_BYTES>>>(x, fc1_w, fc1_b, alpha_b, phi_w, phi_b,
                                          bn_gamma, bn_beta, bn_mean, bn_var, out);
}

// round 12
// speedup vs baseline: 1.2432x; 1.2006x over previous
#include <cuda_runtime.h>
#include <cuda_bf16.h>

#define TPB 256
#define NWARP 8
#define LOCW 12

// Pre-transposed alpha_w: g_awT[h*64 + c2] = alpha_w[c2*64 + h]
__device__ float g_awT[64 * 64];
// Fragment-packed bf16-split B for mma.m16n8k16: (kstep 0..17, ntile 0..7, lane 0..31)
// uint4 = { bhi0, bhi1, blo0, blo1 }
__device__ uint4 g_Bf[18 * 8 * 32];

// Unambiguous bf16x2 pack: .x (lower address / low 16 bits) = lo, .y = hi.
__device__ __forceinline__ unsigned bpack(float lo, float hi) {
    __nv_bfloat162 t;
    t.x = __float2bfloat16(lo);
    t.y = __float2bfloat16(hi);
    return *reinterpret_cast<unsigned*>(&t);
}
__device__ __forceinline__ float bf16val(float v) {
    return __bfloat162float(__float2bfloat16(v));
}

__global__ void prep_kernel(const float* __restrict__ aw, const float* __restrict__ pw) {
    int i = blockIdx.x * blockDim.x + threadIdx.x;
    if (i < 4096) { int hh = i >> 6, c2 = i & 63; g_awT[i] = aw[c2 * 64 + hh]; }
    if (i < 4608) {
        int ks  = i >> 8;
        int rem = i & 255;
        int nt  = rem >> 5, t = rem & 31;
        int n   = t >> 2, k0 = (t & 3) * 2;
        int h   = nt * 8 + n;
        int j   = ks * 16 + k0;
        float v0 = pw[j * 64 + h],       v1 = pw[(j + 1) * 64 + h];
        float v2 = pw[(j + 8) * 64 + h], v3 = pw[(j + 9) * 64 + h];
        unsigned bhi0 = bpack(v0, v1);
        unsigned bhi1 = bpack(v2, v3);
        unsigned blo0 = bpack(v0 - bf16val(v0), v1 - bf16val(v1));
        unsigned blo1 = bpack(v2 - bf16val(v2), v3 - bf16val(v3));
        g_Bf[i] = make_uint4(bhi0, bhi1, blo0, blo1);
    }
}

__device__ __forceinline__ void mma_bf16(float* d, unsigned a0, unsigned a1,
                                         unsigned a2, unsigned a3,
                                         unsigned b0, unsigned b1) {
    asm volatile(
        "mma.sync.aligned.m16n8k16.row.col.f32.bf16.bf16.f32 "
        "{%0,%1,%2,%3}, {%4,%5,%6,%7}, {%8,%9}, {%0,%1,%2,%3};"
        : "+f"(d[0]), "+f"(d[1]), "+f"(d[2]), "+f"(d[3])
        : "r"(a0), "r"(a1), "r"(a2), "r"(a3), "r"(b0), "r"(b1));
}

// Shared layout (floats):
//   [0      .. 9504)  sh_x   : 32 ch * 3 rows * 99 (stride 297)  -> aliased as sh_out (96*65)
//   [9504   .. 15648) sh_h   : 96 loc * 64 hidden
//   [15648  .. 15744) sh_proj: 96
//   [15744  .. 15840) sh_pb  : 96
//   [15840  .. 16128) sh_f   : 288 ints (j -> sh_x base offset)
#define SMEM_FLOATS 16128
#define SMEM_BYTES  (SMEM_FLOATS * 4)

__global__ __launch_bounds__(TPB, 3)
void sac_kernel(const float* __restrict__ x,
                const float* __restrict__ fc1_w, const float* __restrict__ fc1_b,
                const float* __restrict__ alpha_b,
                const float* __restrict__ phi_b,
                const float* __restrict__ bn_gamma, const float* __restrict__ bn_beta,
                const float* __restrict__ bn_mean, const float* __restrict__ bn_var,
                float* __restrict__ out)
{
    extern __shared__ float smem[];
    float* sh_x    = smem;
    float* sh_h    = smem + 9504;
    float* sh_proj = smem + 15648;
    float* sh_pb   = smem + 15744;
    int*   sh_f    = (int*)(smem + 15840);
    float* sh_out  = smem;   // aliases sh_x after GEMM (guarded by __syncthreads)

    const int y    = blockIdx.x;
    const int b    = blockIdx.y;
    const int tid  = threadIdx.x;
    const int warp = tid >> 5;
    const int lane = tid & 31;

    // ---------------- phase 0: stage x rows + build f-table ----------------
    const float* xb = x + (size_t)b * 32 * 9216;
    for (int i = tid; i < 32 * 3 * 98; i += TPB) {
        int c = i / 294, rem = i - c * 294;
        int r = rem / 98, cc = rem - r * 98;
        int gy = y + r - 1, gx = cc - 1;
        float v = 0.f;
        if ((unsigned)gy < 96u && (unsigned)gx < 96u)
            v = xb[(c * 96 + gy) * 96 + gx];
        sh_x[c * 297 + r * 99 + cc] = v;
    }
    for (int i = tid; i < 288; i += TPB) {      // FIX: 288 entries > 256 threads
        int c = i / 9, rm = i % 9;
        sh_f[i] = c * 297 + (rm / 3) * 99 + (rm % 3);
    }
    __syncthreads();

    // ---------------- phase 1: stats + fc1 hidden (all 8 warps) ----------------
    const float inv288 = 1.0f / 288.0f;
    const float invPr  = 1.0f / (288.0f + 1e-6f);

    {
        float pbw[9];
        #pragma unroll
        for (int k = 0; k < 9; k++) pbw[k] = __ldg(&phi_b[lane * 9 + k]);
        float w1c[5], w1c2[5];
        #pragma unroll
        for (int k = 0; k < 5; k++) {
            w1c[k]  = __ldg(&fc1_w[lane * 5 + k]);
            w1c2[k] = __ldg(&fc1_w[(lane + 32) * 5 + k]);
        }
        const float b1  = __ldg(&fc1_b[lane]);
        const float b1b = __ldg(&fc1_b[lane + 32]);

        for (int li = warp; li < 96; li += NWARP) {
            float v[9];
            const float* base = sh_x + lane * 297 + li;
            #pragma unroll
            for (int r = 0; r < 3; r++)
                #pragma unroll
                for (int kc = 0; kc < 3; kc++)
                    v[r * 3 + kc] = base[r * 99 + kc];

            float S1 = 0.f, S2 = 0.f, S3 = 0.f, S4 = 0.f, pbp = 0.f;
            float mn = v[0], mx = v[0];
            #pragma unroll
            for (int k = 0; k < 9; k++) {
                float vk = v[k], v2 = vk * vk;
                S1 += vk; S2 += v2; S3 += v2 * vk; S4 += v2 * v2;
                mn = fminf(mn, vk); mx = fmaxf(mx, vk);
                pbp += pbw[k] * vk;
            }
            #pragma unroll
            for (int o = 16; o; o >>= 1) {
                S1  += __shfl_xor_sync(0xffffffffu, S1,  o);
                S2  += __shfl_xor_sync(0xffffffffu, S2,  o);
                S3  += __shfl_xor_sync(0xffffffffu, S3,  o);
                S4  += __shfl_xor_sync(0xffffffffu, S4,  o);
                pbp += __shfl_xor_sync(0xffffffffu, pbp, o);
                mn = fminf(mn, __shfl_xor_sync(0xffffffffu, mn, o));
                mx = fmaxf(mx, __shfl_xor_sync(0xffffffffu, mx, o));
            }
            float mu = S1 * inv288;
            float r2 = S2 * inv288, r3 = S3 * inv288, r4 = S4 * inv288;
            float mu2 = mu * mu;
            float m2 = r2 - mu2;
            float m3 = r3 - mu * (3.0f * r2 - 2.0f * mu2);
            float m4 = r4 - mu * (4.0f * r3 - mu * (6.0f * r2 - 3.0f * mu2));
            float sigma = sqrtf(m2 + 1e-6f);
            float q = sigma + 1e-6f, iq = 1.0f / q, iq2 = iq * iq;
            float gam = m3 * iq2 * iq;
            float kap = m4 * iq2 * iq2 - 3.0f;

            // register SIMD histogram
            unsigned long long nib = 0ULL;
            float denom = (mx - mn) + 1e-6f;
            #pragma unroll
            for (int k = 0; k < 9; k++) {
                float pn = (v[k] - mn) / denom;
                int bi = (int)(pn * 15.0f);
                bi = max(0, min(15, bi));
                nib += 1ULL << (bi * 4);
            }
            unsigned long long A  =  nib       & 0x0F0F0F0F0F0F0F0FULL;
            unsigned long long Bp = (nib >> 4) & 0x0F0F0F0F0F0F0F0FULL;
            #pragma unroll
            for (int o = 1; o <= 8; o <<= 1) {
                A  += __shfl_xor_sync(0xffffffffu, A,  o);
                Bp += __shfl_xor_sync(0xffffffffu, Bp, o);
            }
            unsigned long long A0 =  A        & 0x00FF00FF00FF00FFULL;
            unsigned long long A1 = (A  >> 8) & 0x00FF00FF00FF00FFULL;
            unsigned long long B0 =  Bp       & 0x00FF00FF00FF00FFULL;
            unsigned long long B1 = (Bp >> 8) & 0x00FF00FF00FF00FFULL;
            A0 += __shfl_xor_sync(0xffffffffu, A0, 16);
            A1 += __shfl_xor_sync(0xffffffffu, A1, 16);
            B0 += __shfl_xor_sync(0xffffffffu, B0, 16);
            B1 += __shfl_xor_sync(0xffffffffu, B1, 16);

            float ent = 0.f;
            if (lane < 16) {
                unsigned long long w = (lane & 1) ? ((lane & 2) ? B1 : B0)
                                                  : ((lane & 2) ? A1 : A0);
                unsigned cnt = (unsigned)(w >> ((lane >> 2) * 16)) & 0xFFFFu;
                float prob = (float)cnt * invPr;
                ent = -prob * logf(prob + 1e-9f);
            }
            #pragma unroll
            for (int o = 16; o; o >>= 1)
                ent += __shfl_xor_sync(0xffffffffu, ent, o);

            float ss[5] = {mu, sigma, gam, kap, ent};
            float h0 = b1, h1 = b1b;
            #pragma unroll
            for (int k = 0; k < 5; k++) { h0 += w1c[k] * ss[k]; h1 += w1c2[k] * ss[k]; }
            sh_h[li * 64 + lane]      = fmaxf(h0, 0.f);
            sh_h[li * 64 + lane + 32] = fmaxf(h1, 0.f);
            if (lane == 0) sh_pb[li] = pbp;
        }
    }
    __syncthreads();

    // ---------------- phase 2: phi GEMM on tensor cores (warps 0..5) + proj ----------
    if (warp < 6) {
        const int gr = lane >> 2, gc = lane & 3;
        const int r0 = warp * 16 + gr;          // rows r0 and r0+8, all < 96
        float d[8][4];
        #pragma unroll
        for (int nt = 0; nt < 8; nt++)
            #pragma unroll
            for (int q = 0; q < 4; q++) d[nt][q] = 0.f;

        const int jc0 = 2 * gc, jc2 = 2 * gc + 8;
        for (int ks = 0; ks < 18; ks++) {
            const int jb = ks * 16;
            const int f0 = sh_f[jb + jc0], f1 = sh_f[jb + jc0 + 1];
            const int f2 = sh_f[jb + jc2], f3 = sh_f[jb + jc2 + 1];
            // A fragment: 2 rows x 4 k-cols
            float v00 = sh_x[f0 + r0],     v01 = sh_x[f1 + r0];
            float v10 = sh_x[f0 + r0 + 8], v11 = sh_x[f1 + r0 + 8];
            float v20 = sh_x[f2 + r0],     v21 = sh_x[f3 + r0];
            float v30 = sh_x[f2 + r0 + 8], v31 = sh_x[f3 + r0 + 8];
            unsigned ah0 = bpack(v00, v01);
            unsigned ah1 = bpack(v10, v11);
            unsigned ah2 = bpack(v20, v21);
            unsigned ah3 = bpack(v30, v31);
            unsigned al0 = bpack(v00 - bf16val(v00), v01 - bf16val(v01));
            unsigned al1 = bpack(v10 - bf16val(v10), v11 - bf16val(v11));
            unsigned al2 = bpack(v20 - bf16val(v20), v21 - bf16val(v21));
            unsigned al3 = bpack(v30 - bf16val(v30), v31 - bf16val(v31));
            #pragma unroll
            for (int nt = 0; nt < 8; nt++) {
                const uint4 bf = __ldg(&g_Bf[(ks * 8 + nt) * 32 + lane]);
                mma_bf16(d[nt], ah0, ah1, ah2, ah3, bf.x, bf.y);   // A_hi * B_hi
                mma_bf16(d[nt], ah0, ah1, ah2, ah3, bf.z, bf.w);   // A_hi * B_lo
                mma_bf16(d[nt], al0, al1, al2, al3, bf.x, bf.y);   // A_lo * B_hi
            }
        }

        // proj: pr[l] = sum_h h[l][h] * D[l][h]  (fragments hold D[l][h])
        float pr0 = 0.f, pr1 = 0.f;
        #pragma unroll
        for (int nt = 0; nt < 8; nt++) {
            const float2 h0v = *(const float2*)(sh_h + r0 * 64 + nt * 8 + 2 * gc);
            const float2 h1v = *(const float2*)(sh_h + (r0 + 8) * 64 + nt * 8 + 2 * gc);
            pr0 += d[nt][0] * h0v.x + d[nt][1] * h0v.y;
            pr1 += d[nt][2] * h1v.x + d[nt][3] * h1v.y;
        }
        pr0 += __shfl_xor_sync(0xffffffffu, pr0, 1);
        pr0 += __shfl_xor_sync(0xffffffffu, pr0, 2);
        pr1 += __shfl_xor_sync(0xffffffffu, pr1, 1);
        pr1 += __shfl_xor_sync(0xffffffffu, pr1, 2);
        if (gc == 0) {
            sh_proj[r0]     = pr0 + sh_pb[r0];
            sh_proj[r0 + 8] = pr1 + sh_pb[r0 + 8];
        }
    }
    __syncthreads();   // proj done; also retires sh_x reads before sh_out alias writes

    // ---------------- phase 3: alpha GEMM + BN + SiLU -> sh_out ----------------
    const int x0  = warp * LOCW;
    const int c20 = 2 * lane;
    {
        float a0[LOCW], a1[LOCW];
        float ab0 = __ldg(&alpha_b[c20]), ab1 = __ldg(&alpha_b[c20 + 1]);
        #pragma unroll
        for (int l = 0; l < LOCW; l++) { a0[l] = ab0; a1[l] = ab1; }
        const float2* awT = (const float2*)g_awT;
        for (int hh = 0; hh < 64; hh += 4) {
            float2 w0 = __ldg(&awT[(hh + 0) * 32 + lane]);
            float2 w1 = __ldg(&awT[(hh + 1) * 32 + lane]);
            float2 w2 = __ldg(&awT[(hh + 2) * 32 + lane]);
            float2 w3 = __ldg(&awT[(hh + 3) * 32 + lane]);
            #pragma unroll
            for (int l = 0; l < LOCW; l++) {
                const float4 hv = *(const float4*)(sh_h + (x0 + l) * 64 + hh);
                a0[l] += w0.x * hv.x + w1.x * hv.y + w2.x * hv.z + w3.x * hv.w;
                a1[l] += w0.y * hv.x + w1.y * hv.y + w2.y * hv.z + w3.y * hv.w;
            }
        }
        float inv0 = __ldg(&bn_gamma[c20])     / sqrtf(__ldg(&bn_var[c20])     + 1e-5f);
        float inv1 = __ldg(&bn_gamma[c20 + 1]) / sqrtf(__ldg(&bn_var[c20 + 1]) + 1e-5f);
        float m0 = __ldg(&bn_mean[c20]), m1 = __ldg(&bn_mean[c20 + 1]);
        float be0 = __ldg(&bn_beta[c20]), be1 = __ldg(&bn_beta[c20 + 1]);
        float yy[2 * LOCW];
        #pragma unroll
        for (int l = 0; l < LOCW; l++) {
            float pj = sh_proj[x0 + l];
            float y0 = (a0[l] * pj - m0) * inv0 + be0;
            float y1 = (a1[l] * pj - m1) * inv1 + be1;
            yy[2 * l]     = y0 / (1.0f + __expf(-y0));
            yy[2 * l + 1] = y1 / (1.0f + __expf(-y1));
        }
        __syncthreads();
        #pragma unroll
        for (int l = 0; l < LOCW; l++) {
            sh_out[(x0 + l) * 65 + c20]     = yy[2 * l];
            sh_out[(x0 + l) * 65 + c20 + 1] = yy[2 * l + 1];
        }
    }
    __syncthreads();

    // ---------------- phase 4: coalesced global write ----------------
    float* ob = out + (size_t)b * 64 * 9216 + y * 96;
    for (int i = tid; i < 6144; i += TPB) {
        int c2 = i / 96;
        int xx = i - c2 * 96;
        ob[(size_t)c2 * 9216 + xx] = sh_out[xx * 65 + c2];
    }
}

extern "C" void kernel_launch(void* const* d_in, const int* in_sizes, int n_in,
                              void* d_out, int out_size) {
    int ix = -1, ifc1w = -1, iaw = -1, ipw = -1, ipb = -1;
    int idx64[8]; int n64 = 0;
    for (int i = 0; i < n_in; i++) {
        switch (in_sizes[i]) {
            case 1179648: ix    = i; break;
            case 18432:   ipw   = i; break;
            case 4096:    iaw   = i; break;
            case 320:     ifc1w = i; break;
            case 288:     ipb   = i; break;
            case 64:      if (n64 < 8) idx64[n64++] = i; break;
            default: break;
        }
    }
    int ifc1b, iab, ibg, ibb, ibm, ibv;
    if (ix < 0 || ipw < 0 || iaw < 0 || ifc1w < 0 || ipb < 0 || n64 < 6) {
        ix = 0; ifc1w = 1; ifc1b = 2; iaw = 3; iab = 4; ipw = 5; ipb = 6;
        ibg = 7; ibb = 8; ibm = 9; ibv = 10;
    } else if (ix == 0) {
        ifc1b = idx64[0]; iab = idx64[1]; ibg = idx64[2];
        ibb   = idx64[3]; ibm = idx64[4]; ibv = idx64[5];
    } else {
        iab   = idx64[0]; ibb = idx64[1]; ibg = idx64[2];
        ibm   = idx64[3]; ibv = idx64[4]; ifc1b = idx64[5];
    }

    const float* x        = (const float*)d_in[ix];
    const float* fc1_w    = (const float*)d_in[ifc1w];
    const float* fc1_b    = (const float*)d_in[ifc1b];
    const float* alpha_w  = (const float*)d_in[iaw];
    const float* alpha_b  = (const float*)d_in[iab];
    const float* phi_w    = (const float*)d_in[ipw];
    const float* phi_b    = (const float*)d_in[ipb];
    const float* bn_gamma = (const float*)d_in[ibg];
    const float* bn_beta  = (const float*)d_in[ibb];
    const float* bn_mean  = (const float*)d_in[ibm];
    const float* bn_var   = (const float*)d_in[ibv];
    float* out = (float*)d_out;

    cudaFuncSetAttribute(sac_kernel, cudaFuncAttributeMaxDynamicSharedMemorySize, SMEM_BYTES);

    prep_kernel<<<18, 256>>>(alpha_w, phi_w);
    dim3 grid(96, 4);
    sac_kernel<<<grid, TPB, SMEM_BYTES>>>(x, fc1_w, fc1_b, alpha_b, phi_b,
                                          bn_gamma, bn_beta, bn_mean, bn_var, out);
}

// round 13
// speedup vs baseline: 1.3486x; 1.0847x over previous
#include <cuda_runtime.h>
#include <cuda_bf16.h>

#define TPB 256
#define NWARP 8

// Fragment-packed bf16-split B for phi MMA: (kstep 0..17, ntile 0..7, lane 0..31)
__device__ uint4 g_Bf[18 * 8 * 32];
// Fragment-packed bf16-split B for alpha MMA: (kstep 0..3, ntile 0..7, lane 0..31)
__device__ uint4 g_Af[4 * 8 * 32];
// Fused BN/alpha params per c2: {inv, mean, beta, alpha_b}
__device__ float4 g_bn[64];

// Unambiguous bf16x2 pack: .x (low 16 bits) = lo, .y = hi.
__device__ __forceinline__ unsigned bpack(float lo, float hi) {
    __nv_bfloat162 t;
    t.x = __float2bfloat16(lo);
    t.y = __float2bfloat16(hi);
    return *reinterpret_cast<unsigned*>(&t);
}
__device__ __forceinline__ float bf16val(float v) {
    return __bfloat162float(__float2bfloat16(v));
}

__global__ void prep_kernel(const float* __restrict__ aw, const float* __restrict__ pw,
                            const float* __restrict__ ab, const float* __restrict__ bg,
                            const float* __restrict__ bb, const float* __restrict__ bm,
                            const float* __restrict__ bv) {
    int i = blockIdx.x * blockDim.x + threadIdx.x;
    if (i < 4608) {   // phi B fragments: B[n=h][k=j] = pw[j*64+h]
        int ks  = i >> 8;
        int rem = i & 255;
        int nt  = rem >> 5, t = rem & 31;
        int n   = t >> 2, k0 = (t & 3) * 2;
        int h   = nt * 8 + n;
        int j   = ks * 16 + k0;
        float v0 = pw[j * 64 + h],       v1 = pw[(j + 1) * 64 + h];
        float v2 = pw[(j + 8) * 64 + h], v3 = pw[(j + 9) * 64 + h];
        g_Bf[i] = make_uint4(bpack(v0, v1), bpack(v2, v3),
                             bpack(v0 - bf16val(v0), v1 - bf16val(v1)),
                             bpack(v2 - bf16val(v2), v3 - bf16val(v3)));
    }
    if (i < 1024) {   // alpha B fragments: B[n=c2][k=h] = aw[c2*64+h]
        int ks  = i >> 8;
        int rem = i & 255;
        int nt  = rem >> 5, t = rem & 31;
        int n   = t >> 2, k0 = (t & 3) * 2;
        int c2  = nt * 8 + n;
        int h   = ks * 16 + k0;
        float v0 = aw[c2 * 64 + h],     v1 = aw[c2 * 64 + h + 1];
        float v2 = aw[c2 * 64 + h + 8], v3 = aw[c2 * 64 + h + 9];
        g_Af[i] = make_uint4(bpack(v0, v1), bpack(v2, v3),
                             bpack(v0 - bf16val(v0), v1 - bf16val(v1)),
                             bpack(v2 - bf16val(v2), v3 - bf16val(v3)));
    }
    if (i < 64) {
        float inv = bg[i] / sqrtf(bv[i] + 1e-5f);
        g_bn[i] = make_float4(inv, bm[i], bb[i], ab[i]);
    }
}

__device__ __forceinline__ void mma_bf16(float* d, unsigned a0, unsigned a1,
                                         unsigned a2, unsigned a3,
                                         unsigned b0, unsigned b1) {
    asm volatile(
        "mma.sync.aligned.m16n8k16.row.col.f32.bf16.bf16.f32 "
        "{%0,%1,%2,%3}, {%4,%5,%6,%7}, {%8,%9}, {%0,%1,%2,%3};"
        : "+f"(d[0]), "+f"(d[1]), "+f"(d[2]), "+f"(d[3])
        : "r"(a0), "r"(a1), "r"(a2), "r"(a3), "r"(b0), "r"(b1));
}

// Shared layout (floats):
//   [0      .. 9504)  sh_x   : 32 ch * 3 rows * 99 (stride 297)  -> aliased as sh_out (96*65)
//   [9504   .. 15648) sh_h   : 96 loc * 64 hidden
//   [15648  .. 15744) sh_proj: 96
//   [15744  .. 15840) sh_pb  : 96
//   [15840  .. 16128) sh_f   : 288 ints (j -> sh_x base offset)
#define SMEM_FLOATS 16128
#define SMEM_BYTES  (SMEM_FLOATS * 4)

__global__ __launch_bounds__(TPB, 3)
void sac_kernel(const float* __restrict__ x,
                const float* __restrict__ fc1_w, const float* __restrict__ fc1_b,
                const float* __restrict__ phi_b,
                float* __restrict__ out)
{
    extern __shared__ float smem[];
    float* sh_x    = smem;
    float* sh_h    = smem + 9504;
    float* sh_proj = smem + 15648;
    float* sh_pb   = smem + 15744;
    int*   sh_f    = (int*)(smem + 15840);
    float* sh_out  = smem;   // aliases sh_x after phi MMA (guarded by __syncthreads)

    const int y    = blockIdx.x;
    const int b    = blockIdx.y;
    const int tid  = threadIdx.x;
    const int warp = tid >> 5;
    const int lane = tid & 31;

    // ---------------- phase 0: stage x rows + build f-table ----------------
    const float* xb = x + (size_t)b * 32 * 9216;
    for (int i = tid; i < 32 * 3 * 98; i += TPB) {
        int c = i / 294, rem = i - c * 294;
        int r = rem / 98, cc = rem - r * 98;
        int gy = y + r - 1, gx = cc - 1;
        float v = 0.f;
        if ((unsigned)gy < 96u && (unsigned)gx < 96u)
            v = xb[(c * 96 + gy) * 96 + gx];
        sh_x[c * 297 + r * 99 + cc] = v;
    }
    for (int i = tid; i < 288; i += TPB) {
        int c = i / 9, rm = i % 9;
        sh_f[i] = c * 297 + (rm / 3) * 99 + (rm % 3);
    }
    __syncthreads();

    // ---------------- phase 1: stats + fc1 hidden (all 8 warps) ----------------
    const float inv288 = 1.0f / 288.0f;
    const float invPr  = 1.0f / (288.0f + 1e-6f);

    {
        float pbw[9];
        #pragma unroll
        for (int k = 0; k < 9; k++) pbw[k] = __ldg(&phi_b[lane * 9 + k]);
        float w1c[5], w1c2[5];
        #pragma unroll
        for (int k = 0; k < 5; k++) {
            w1c[k]  = __ldg(&fc1_w[lane * 5 + k]);
            w1c2[k] = __ldg(&fc1_w[(lane + 32) * 5 + k]);
        }
        const float b1  = __ldg(&fc1_b[lane]);
        const float b1b = __ldg(&fc1_b[lane + 32]);

        for (int li = warp; li < 96; li += NWARP) {
            float v[9];
            const float* base = sh_x + lane * 297 + li;
            #pragma unroll
            for (int r = 0; r < 3; r++)
                #pragma unroll
                for (int kc = 0; kc < 3; kc++)
                    v[r * 3 + kc] = base[r * 99 + kc];

            float S1 = 0.f, S2 = 0.f, S3 = 0.f, S4 = 0.f, pbp = 0.f;
            float mn = v[0], mx = v[0];
            #pragma unroll
            for (int k = 0; k < 9; k++) {
                float vk = v[k], v2 = vk * vk;
                S1 += vk; S2 += v2; S3 += v2 * vk; S4 += v2 * v2;
                mn = fminf(mn, vk); mx = fmaxf(mx, vk);
                pbp += pbw[k] * vk;
            }
            #pragma unroll
            for (int o = 16; o; o >>= 1) {
                S1  += __shfl_xor_sync(0xffffffffu, S1,  o);
                S2  += __shfl_xor_sync(0xffffffffu, S2,  o);
                S3  += __shfl_xor_sync(0xffffffffu, S3,  o);
                S4  += __shfl_xor_sync(0xffffffffu, S4,  o);
                pbp += __shfl_xor_sync(0xffffffffu, pbp, o);
                mn = fminf(mn, __shfl_xor_sync(0xffffffffu, mn, o));
                mx = fmaxf(mx, __shfl_xor_sync(0xffffffffu, mx, o));
            }
            float mu = S1 * inv288;
            float r2 = S2 * inv288, r3 = S3 * inv288, r4 = S4 * inv288;
            float mu2 = mu * mu;
            float m2 = r2 - mu2;
            float m3 = r3 - mu * (3.0f * r2 - 2.0f * mu2);
            float m4 = r4 - mu * (4.0f * r3 - mu * (6.0f * r2 - 3.0f * mu2));
            float sigma = sqrtf(m2 + 1e-6f);
            float q = sigma + 1e-6f, iq = 1.0f / q, iq2 = iq * iq;
            float gam = m3 * iq2 * iq;
            float kap = m4 * iq2 * iq2 - 3.0f;

            // register SIMD histogram
            unsigned long long nib = 0ULL;
            float denom = (mx - mn) + 1e-6f;
            #pragma unroll
            for (int k = 0; k < 9; k++) {
                float pn = (v[k] - mn) / denom;
                int bi = (int)(pn * 15.0f);
                bi = max(0, min(15, bi));
                nib += 1ULL << (bi * 4);
            }
            unsigned long long A  =  nib       & 0x0F0F0F0F0F0F0F0FULL;
            unsigned long long Bp = (nib >> 4) & 0x0F0F0F0F0F0F0F0FULL;
            #pragma unroll
            for (int o = 1; o <= 8; o <<= 1) {
                A  += __shfl_xor_sync(0xffffffffu, A,  o);
                Bp += __shfl_xor_sync(0xffffffffu, Bp, o);
            }
            unsigned long long A0 =  A        & 0x00FF00FF00FF00FFULL;
            unsigned long long A1 = (A  >> 8) & 0x00FF00FF00FF00FFULL;
            unsigned long long B0 =  Bp       & 0x00FF00FF00FF00FFULL;
            unsigned long long B1 = (Bp >> 8) & 0x00FF00FF00FF00FFULL;
            A0 += __shfl_xor_sync(0xffffffffu, A0, 16);
            A1 += __shfl_xor_sync(0xffffffffu, A1, 16);
            B0 += __shfl_xor_sync(0xffffffffu, B0, 16);
            B1 += __shfl_xor_sync(0xffffffffu, B1, 16);

            float ent = 0.f;
            if (lane < 16) {
                unsigned long long w = (lane & 1) ? ((lane & 2) ? B1 : B0)
                                                  : ((lane & 2) ? A1 : A0);
                unsigned cnt = (unsigned)(w >> ((lane >> 2) * 16)) & 0xFFFFu;
                float prob = (float)cnt * invPr;
                ent = -prob * logf(prob + 1e-9f);
            }
            #pragma unroll
            for (int o = 16; o; o >>= 1)
                ent += __shfl_xor_sync(0xffffffffu, ent, o);

            float ss[5] = {mu, sigma, gam, kap, ent};
            float h0 = b1, h1 = b1b;
            #pragma unroll
            for (int k = 0; k < 5; k++) { h0 += w1c[k] * ss[k]; h1 += w1c2[k] * ss[k]; }
            sh_h[li * 64 + lane]      = fmaxf(h0, 0.f);
            sh_h[li * 64 + lane + 32] = fmaxf(h1, 0.f);
            if (lane == 0) sh_pb[li] = pbp;
        }
    }
    __syncthreads();

    const int gr = lane >> 2, gc = lane & 3;
    const int r0 = warp * 16 + gr;              // valid for warp < 6

    // ---------------- phase 2: phi GEMM on tensor cores (warps 0..5) + proj ----------
    if (warp < 6) {
        float d[8][4];
        #pragma unroll
        for (int nt = 0; nt < 8; nt++)
            #pragma unroll
            for (int q = 0; q < 4; q++) d[nt][q] = 0.f;

        const int jc0 = 2 * gc, jc2 = 2 * gc + 8;
        for (int ks = 0; ks < 18; ks++) {
            const int jb = ks * 16;
            const int f0 = sh_f[jb + jc0], f1 = sh_f[jb + jc0 + 1];
            const int f2 = sh_f[jb + jc2], f3 = sh_f[jb + jc2 + 1];
            float v00 = sh_x[f0 + r0],     v01 = sh_x[f1 + r0];
            float v10 = sh_x[f0 + r0 + 8], v11 = sh_x[f1 + r0 + 8];
            float v20 = sh_x[f2 + r0],     v21 = sh_x[f3 + r0];
            float v30 = sh_x[f2 + r0 + 8], v31 = sh_x[f3 + r0 + 8];
            unsigned ah0 = bpack(v00, v01);
            unsigned ah1 = bpack(v10, v11);
            unsigned ah2 = bpack(v20, v21);
            unsigned ah3 = bpack(v30, v31);
            unsigned al0 = bpack(v00 - bf16val(v00), v01 - bf16val(v01));
            unsigned al1 = bpack(v10 - bf16val(v10), v11 - bf16val(v11));
            unsigned al2 = bpack(v20 - bf16val(v20), v21 - bf16val(v21));
            unsigned al3 = bpack(v30 - bf16val(v30), v31 - bf16val(v31));
            #pragma unroll
            for (int nt = 0; nt < 8; nt++) {
                const uint4 bf = __ldg(&g_Bf[(ks * 8 + nt) * 32 + lane]);
                mma_bf16(d[nt], ah0, ah1, ah2, ah3, bf.x, bf.y);
                mma_bf16(d[nt], ah0, ah1, ah2, ah3, bf.z, bf.w);
                mma_bf16(d[nt], al0, al1, al2, al3, bf.x, bf.y);
            }
        }

        float pr0 = 0.f, pr1 = 0.f;
        #pragma unroll
        for (int nt = 0; nt < 8; nt++) {
            const float2 h0v = *(const float2*)(sh_h + r0 * 64 + nt * 8 + 2 * gc);
            const float2 h1v = *(const float2*)(sh_h + (r0 + 8) * 64 + nt * 8 + 2 * gc);
            pr0 += d[nt][0] * h0v.x + d[nt][1] * h0v.y;
            pr1 += d[nt][2] * h1v.x + d[nt][3] * h1v.y;
        }
        pr0 += __shfl_xor_sync(0xffffffffu, pr0, 1);
        pr0 += __shfl_xor_sync(0xffffffffu, pr0, 2);
        pr1 += __shfl_xor_sync(0xffffffffu, pr1, 1);
        pr1 += __shfl_xor_sync(0xffffffffu, pr1, 2);
        if (gc == 0) {
            sh_proj[r0]     = pr0 + sh_pb[r0];
            sh_proj[r0 + 8] = pr1 + sh_pb[r0 + 8];
        }
    }
    __syncthreads();   // proj visible; all sh_x reads retired before sh_out alias writes

    // ---------------- phase 3: alpha GEMM on tensor cores (warps 0..5) + BN/SiLU -----
    if (warp < 6) {
        float d2[8][4];
        #pragma unroll
        for (int nt = 0; nt < 8; nt++)
            #pragma unroll
            for (int q = 0; q < 4; q++) d2[nt][q] = 0.f;

        #pragma unroll
        for (int ks = 0; ks < 4; ks++) {
            const float2* hr0 = (const float2*)(sh_h + r0 * 64 + ks * 16);
            const float2* hr1 = (const float2*)(sh_h + (r0 + 8) * 64 + ks * 16);
            float2 p00 = hr0[gc], p01 = hr0[gc + 4];
            float2 p10 = hr1[gc], p11 = hr1[gc + 4];
            unsigned ah0 = bpack(p00.x, p00.y);
            unsigned ah1 = bpack(p10.x, p10.y);
            unsigned ah2 = bpack(p01.x, p01.y);
            unsigned ah3 = bpack(p11.x, p11.y);
            unsigned al0 = bpack(p00.x - bf16val(p00.x), p00.y - bf16val(p00.y));
            unsigned al1 = bpack(p10.x - bf16val(p10.x), p10.y - bf16val(p10.y));
            unsigned al2 = bpack(p01.x - bf16val(p01.x), p01.y - bf16val(p01.y));
            unsigned al3 = bpack(p11.x - bf16val(p11.x), p11.y - bf16val(p11.y));
            #pragma unroll
            for (int nt = 0; nt < 8; nt++) {
                const uint4 bf = __ldg(&g_Af[(ks * 8 + nt) * 32 + lane]);
                mma_bf16(d2[nt], ah0, ah1, ah2, ah3, bf.x, bf.y);
                mma_bf16(d2[nt], ah0, ah1, ah2, ah3, bf.z, bf.w);
                mma_bf16(d2[nt], al0, al1, al2, al3, bf.x, bf.y);
            }
        }

        const float pj0 = sh_proj[r0];
        const float pj1 = sh_proj[r0 + 8];
        #pragma unroll
        for (int nt = 0; nt < 8; nt++) {
            const int c2 = nt * 8 + 2 * gc;
            const float4 bn0 = __ldg(&g_bn[c2]);       // {inv, mean, beta, alpha_b}
            const float4 bn1 = __ldg(&g_bn[c2 + 1]);
            float y00 = ((d2[nt][0] + bn0.w) * pj0 - bn0.y) * bn0.x + bn0.z;
            float y01 = ((d2[nt][1] + bn1.w) * pj0 - bn1.y) * bn1.x + bn1.z;
            float y10 = ((d2[nt][2] + bn0.w) * pj1 - bn0.y) * bn0.x + bn0.z;
            float y11 = ((d2[nt][3] + bn1.w) * pj1 - bn1.y) * bn1.x + bn1.z;
            sh_out[r0 * 65 + c2]           = y00 / (1.0f + __expf(-y00));
            sh_out[r0 * 65 + c2 + 1]       = y01 / (1.0f + __expf(-y01));
            sh_out[(r0 + 8) * 65 + c2]     = y10 / (1.0f + __expf(-y10));
            sh_out[(r0 + 8) * 65 + c2 + 1] = y11 / (1.0f + __expf(-y11));
        }
    }
    __syncthreads();

    // ---------------- phase 4: coalesced global write ----------------
    float* ob = out + (size_t)b * 64 * 9216 + y * 96;
    for (int i = tid; i < 6144; i += TPB) {
        int c2 = i / 96;
        int xx = i - c2 * 96;
        ob[(size_t)c2 * 9216 + xx] = sh_out[xx * 65 + c2];
    }
}

extern "C" void kernel_launch(void* const* d_in, const int* in_sizes, int n_in,
                              void* d_out, int out_size) {
    int ix = -1, ifc1w = -1, iaw = -1, ipw = -1, ipb = -1;
    int idx64[8]; int n64 = 0;
    for (int i = 0; i < n_in; i++) {
        switch (in_sizes[i]) {
            case 1179648: ix    = i; break;
            case 18432:   ipw   = i; break;
            case 4096:    iaw   = i; break;
            case 320:     ifc1w = i; break;
            case 288:     ipb   = i; break;
            case 64:      if (n64 < 8) idx64[n64++] = i; break;
            default: break;
        }
    }
    int ifc1b, iab, ibg, ibb, ibm, ibv;
    if (ix < 0 || ipw < 0 || iaw < 0 || ifc1w < 0 || ipb < 0 || n64 < 6) {
        ix = 0; ifc1w = 1; ifc1b = 2; iaw = 3; iab = 4; ipw = 5; ipb = 6;
        ibg = 7; ibb = 8; ibm = 9; ibv = 10;
    } else if (ix == 0) {
        ifc1b = idx64[0]; iab = idx64[1]; ibg = idx64[2];
        ibb   = idx64[3]; ibm = idx64[4]; ibv = idx64[5];
    } else {
        iab   = idx64[0]; ibb = idx64[1]; ibg = idx64[2];
        ibm   = idx64[3]; ibv = idx64[4]; ifc1b = idx64[5];
    }

    const float* x        = (const float*)d_in[ix];
    const float* fc1_w    = (const float*)d_in[ifc1w];
    const float* fc1_b    = (const float*)d_in[ifc1b];
    const float* alpha_w  = (const float*)d_in[iaw];
    const float* alpha_b  = (const float*)d_in[iab];
    const float* phi_w    = (const float*)d_in[ipw];
    const float* phi_b    = (const float*)d_in[ipb];
    const float* bn_gamma = (const float*)d_in[ibg];
    const float* bn_beta  = (const float*)d_in[ibb];
    const float* bn_mean  = (const float*)d_in[ibm];
    const float* bn_var   = (const float*)d_in[ibv];
    float* out = (float*)d_out;

    cudaFuncSetAttribute(sac_kernel, cudaFuncAttributeMaxDynamicSharedMemorySize, SMEM_BYTES);

    prep_kernel<<<18, 256>>>(alpha_w, phi_w, alpha_b, bn_gamma, bn_beta, bn_mean, bn_var);
    dim3 grid(96, 4);
    sac_kernel<<<grid, TPB, SMEM_BYTES>>>(x, fc1_w, fc1_b, phi_b, out);
}

// round 14
// speedup vs baseline: 1.3554x; 1.0051x over previous
#include <cuda_runtime.h>
#include <cuda_bf16.h>

#define TPB 256
#define NWARP 8

// Fragment-packed bf16-split B for phi MMA: (kstep 0..17, ntile 0..7, lane 0..31)
__device__ uint4 g_Bf[18 * 8 * 32];
// Fragment-packed bf16-split B for alpha MMA: (kstep 0..3, ntile 0..7, lane 0..31)
__device__ uint4 g_Af[4 * 8 * 32];
// Fused BN/alpha params per c2: {inv, mean, beta, alpha_b}
__device__ float4 g_bn[64];

__device__ __forceinline__ unsigned bpack(float lo, float hi) {
    __nv_bfloat162 t;
    t.x = __float2bfloat16(lo);
    t.y = __float2bfloat16(hi);
    return *reinterpret_cast<unsigned*>(&t);
}
__device__ __forceinline__ float bf16val(float v) {
    return __bfloat162float(__float2bfloat16(v));
}

__global__ void prep_kernel(const float* __restrict__ aw, const float* __restrict__ pw,
                            const float* __restrict__ ab, const float* __restrict__ bg,
                            const float* __restrict__ bb, const float* __restrict__ bm,
                            const float* __restrict__ bv) {
    int i = blockIdx.x * blockDim.x + threadIdx.x;
    if (i < 4608) {   // phi B fragments: B[n=h][k=j] = pw[j*64+h]
        int ks  = i >> 8;
        int rem = i & 255;
        int nt  = rem >> 5, t = rem & 31;
        int n   = t >> 2, k0 = (t & 3) * 2;
        int h   = nt * 8 + n;
        int j   = ks * 16 + k0;
        float v0 = pw[j * 64 + h],       v1 = pw[(j + 1) * 64 + h];
        float v2 = pw[(j + 8) * 64 + h], v3 = pw[(j + 9) * 64 + h];
        g_Bf[i] = make_uint4(bpack(v0, v1), bpack(v2, v3),
                             bpack(v0 - bf16val(v0), v1 - bf16val(v1)),
                             bpack(v2 - bf16val(v2), v3 - bf16val(v3)));
    }
    if (i < 1024) {   // alpha B fragments: B[n=c2][k=h] = aw[c2*64+h]
        int ks  = i >> 8;
        int rem = i & 255;
        int nt  = rem >> 5, t = rem & 31;
        int n   = t >> 2, k0 = (t & 3) * 2;
        int c2  = nt * 8 + n;
        int h   = ks * 16 + k0;
        float v0 = aw[c2 * 64 + h],     v1 = aw[c2 * 64 + h + 1];
        float v2 = aw[c2 * 64 + h + 8], v3 = aw[c2 * 64 + h + 9];
        g_Af[i] = make_uint4(bpack(v0, v1), bpack(v2, v3),
                             bpack(v0 - bf16val(v0), v1 - bf16val(v1)),
                             bpack(v2 - bf16val(v2), v3 - bf16val(v3)));
    }
    if (i < 64) {
        float inv = bg[i] / sqrtf(bv[i] + 1e-5f);
        g_bn[i] = make_float4(inv, bm[i], bb[i], ab[i]);
    }
}

__device__ __forceinline__ void mma_bf16(float* d, unsigned a0, unsigned a1,
                                         unsigned a2, unsigned a3,
                                         unsigned b0, unsigned b1) {
    asm volatile(
        "mma.sync.aligned.m16n8k16.row.col.f32.bf16.bf16.f32 "
        "{%0,%1,%2,%3}, {%4,%5,%6,%7}, {%8,%9}, {%0,%1,%2,%3};"
        : "+f"(d[0]), "+f"(d[1]), "+f"(d[2]), "+f"(d[3])
        : "r"(a0), "r"(a1), "r"(a2), "r"(a3), "r"(b0), "r"(b1));
}

// Shared layout (floats):
//   [0      .. 9504)  sh_x   : 32 ch * 3 rows * 99 (stride 297)  -> aliased as sh_out (96*65)
//   [9504   .. 15648) sh_h   : 96 loc * 64 hidden
//   [15648  .. 15744) sh_proj: 96
//   [15744  .. 15840) sh_pb  : 96
//   [15840  .. 16128) sh_f   : 288 ints (j -> sh_x base offset)
#define SMEM_FLOATS 16128
#define SMEM_BYTES  (SMEM_FLOATS * 4)

__global__ __launch_bounds__(TPB, 3)
void sac_kernel(const float* __restrict__ x,
                const float* __restrict__ fc1_w, const float* __restrict__ fc1_b,
                const float* __restrict__ phi_b,
                float* __restrict__ out)
{
    extern __shared__ float smem[];
    float* sh_x    = smem;
    float* sh_h    = smem + 9504;
    float* sh_proj = smem + 15648;
    float* sh_pb   = smem + 15744;
    int*   sh_f    = (int*)(smem + 15840);
    float* sh_out  = smem;   // aliases sh_x after phi MMA (guarded by __syncthreads)

    const int y    = blockIdx.x;
    const int b    = blockIdx.y;
    const int tid  = threadIdx.x;
    const int warp = tid >> 5;
    const int lane = tid & 31;

    // ---------------- phase 0: stage x rows + build f-table ----------------
    const float* xb = x + (size_t)b * 32 * 9216;
    for (int i = tid; i < 32 * 3 * 98; i += TPB) {
        int c = i / 294, rem = i - c * 294;
        int r = rem / 98, cc = rem - r * 98;
        int gy = y + r - 1, gx = cc - 1;
        float v = 0.f;
        if ((unsigned)gy < 96u && (unsigned)gx < 96u)
            v = xb[(c * 96 + gy) * 96 + gx];
        sh_x[c * 297 + r * 99 + cc] = v;
    }
    for (int i = tid; i < 288; i += TPB) {
        int c = i / 9, rm = i % 9;
        sh_f[i] = c * 297 + (rm / 3) * 99 + (rm % 3);
    }
    __syncthreads();

    // ---------------- phase 1: stats + fc1, TWO locations per iteration ----------------
    const float inv288 = 1.0f / 288.0f;
    const float invPr  = 1.0f / (288.0f + 1e-6f);

    {
        float pbw[9];
        #pragma unroll
        for (int k = 0; k < 9; k++) pbw[k] = __ldg(&phi_b[lane * 9 + k]);
        float w1c[5], w1c2[5];
        #pragma unroll
        for (int k = 0; k < 5; k++) {
            w1c[k]  = __ldg(&fc1_w[lane * 5 + k]);
            w1c2[k] = __ldg(&fc1_w[(lane + 32) * 5 + k]);
        }
        const float b1  = __ldg(&fc1_b[lane]);
        const float b1b = __ldg(&fc1_b[lane + 32]);

        #pragma unroll 1
        for (int t = 0; t < 6; t++) {
            const int l0 = t * 8 + warp;     // 0..47
            const int l1 = l0 + 48;          // 48..95
            const float* base0 = sh_x + lane * 297 + l0;
            const float* base1 = sh_x + lane * 297 + l1;

            float S1a = 0.f, S2a = 0.f, S3a = 0.f, S4a = 0.f, pba = 0.f, mna, mxa;
            float S1b = 0.f, S2b = 0.f, S3b = 0.f, S4b = 0.f, pbb = 0.f, mnb, mxb;
            {
                float v[9];
                #pragma unroll
                for (int r = 0; r < 3; r++)
                    #pragma unroll
                    for (int kc = 0; kc < 3; kc++)
                        v[r * 3 + kc] = base0[r * 99 + kc];
                mna = v[0]; mxa = v[0];
                #pragma unroll
                for (int k = 0; k < 9; k++) {
                    float vk = v[k], v2 = vk * vk;
                    S1a += vk; S2a += v2; S3a += v2 * vk; S4a += v2 * v2;
                    mna = fminf(mna, vk); mxa = fmaxf(mxa, vk);
                    pba += pbw[k] * vk;
                }
            }
            {
                float v[9];
                #pragma unroll
                for (int r = 0; r < 3; r++)
                    #pragma unroll
                    for (int kc = 0; kc < 3; kc++)
                        v[r * 3 + kc] = base1[r * 99 + kc];
                mnb = v[0]; mxb = v[0];
                #pragma unroll
                for (int k = 0; k < 9; k++) {
                    float vk = v[k], v2 = vk * vk;
                    S1b += vk; S2b += v2; S3b += v2 * vk; S4b += v2 * v2;
                    mnb = fminf(mnb, vk); mxb = fmaxf(mxb, vk);
                    pbb += pbw[k] * vk;
                }
            }
            // joint 14-value butterfly (two locations share the 5-round chain)
            #pragma unroll
            for (int o = 16; o; o >>= 1) {
                S1a += __shfl_xor_sync(0xffffffffu, S1a, o);
                S2a += __shfl_xor_sync(0xffffffffu, S2a, o);
                S3a += __shfl_xor_sync(0xffffffffu, S3a, o);
                S4a += __shfl_xor_sync(0xffffffffu, S4a, o);
                pba += __shfl_xor_sync(0xffffffffu, pba, o);
                mna = fminf(mna, __shfl_xor_sync(0xffffffffu, mna, o));
                mxa = fmaxf(mxa, __shfl_xor_sync(0xffffffffu, mxa, o));
                S1b += __shfl_xor_sync(0xffffffffu, S1b, o);
                S2b += __shfl_xor_sync(0xffffffffu, S2b, o);
                S3b += __shfl_xor_sync(0xffffffffu, S3b, o);
                S4b += __shfl_xor_sync(0xffffffffu, S4b, o);
                pbb += __shfl_xor_sync(0xffffffffu, pbb, o);
                mnb = fminf(mnb, __shfl_xor_sync(0xffffffffu, mnb, o));
                mxb = fmaxf(mxb, __shfl_xor_sync(0xffffffffu, mxb, o));
            }

            // moments -> stats, both locations
            float mu0 = S1a * inv288, mu1 = S1b * inv288;
            float r20 = S2a * inv288, r30 = S3a * inv288, r40 = S4a * inv288;
            float r21 = S2b * inv288, r31 = S3b * inv288, r41 = S4b * inv288;
            float mu20 = mu0 * mu0, mu21 = mu1 * mu1;
            float m20 = r20 - mu20, m21v = r21 - mu21;
            float m30 = r30 - mu0 * (3.0f * r20 - 2.0f * mu20);
            float m31 = r31 - mu1 * (3.0f * r21 - 2.0f * mu21);
            float m40 = r40 - mu0 * (4.0f * r30 - mu0 * (6.0f * r20 - 3.0f * mu20));
            float m41 = r41 - mu1 * (4.0f * r31 - mu1 * (6.0f * r21 - 3.0f * mu21));
            float sg0 = sqrtf(m20 + 1e-6f), sg1 = sqrtf(m21v + 1e-6f);
            float iq0 = 1.0f / (sg0 + 1e-6f), iq1 = 1.0f / (sg1 + 1e-6f);
            float iq20 = iq0 * iq0, iq21 = iq1 * iq1;
            float gm0 = m30 * iq20 * iq0, gm1 = m31 * iq21 * iq1;
            float kp0 = m40 * iq20 * iq20 - 3.0f, kp1 = m41 * iq21 * iq21 - 3.0f;

            // histograms (reload values; binning arithmetic bit-matches reference)
            unsigned long long nib0 = 0ULL, nib1 = 0ULL;
            {
                float den0 = (mxa - mna) + 1e-6f;
                #pragma unroll
                for (int r = 0; r < 3; r++)
                    #pragma unroll
                    for (int kc = 0; kc < 3; kc++) {
                        float pn = (base0[r * 99 + kc] - mna) / den0;
                        int bi = (int)(pn * 15.0f);
                        bi = max(0, min(15, bi));
                        nib0 += 1ULL << (bi * 4);
                    }
                float den1 = (mxb - mnb) + 1e-6f;
                #pragma unroll
                for (int r = 0; r < 3; r++)
                    #pragma unroll
                    for (int kc = 0; kc < 3; kc++) {
                        float pn = (base1[r * 99 + kc] - mnb) / den1;
                        int bi = (int)(pn * 15.0f);
                        bi = max(0, min(15, bi));
                        nib1 += 1ULL << (bi * 4);
                    }
            }
            unsigned long long Aa =  nib0       & 0x0F0F0F0F0F0F0F0FULL;
            unsigned long long Ba = (nib0 >> 4) & 0x0F0F0F0F0F0F0F0FULL;
            unsigned long long Ab =  nib1       & 0x0F0F0F0F0F0F0F0FULL;
            unsigned long long Bb = (nib1 >> 4) & 0x0F0F0F0F0F0F0F0FULL;
            #pragma unroll
            for (int o = 1; o <= 8; o <<= 1) {
                Aa += __shfl_xor_sync(0xffffffffu, Aa, o);
                Ba += __shfl_xor_sync(0xffffffffu, Ba, o);
                Ab += __shfl_xor_sync(0xffffffffu, Ab, o);
                Bb += __shfl_xor_sync(0xffffffffu, Bb, o);
            }
            unsigned long long A0a =  Aa       & 0x00FF00FF00FF00FFULL;
            unsigned long long A1a = (Aa >> 8) & 0x00FF00FF00FF00FFULL;
            unsigned long long B0a =  Ba       & 0x00FF00FF00FF00FFULL;
            unsigned long long B1a = (Ba >> 8) & 0x00FF00FF00FF00FFULL;
            unsigned long long A0b =  Ab       & 0x00FF00FF00FF00FFULL;
            unsigned long long A1b = (Ab >> 8) & 0x00FF00FF00FF00FFULL;
            unsigned long long B0b =  Bb       & 0x00FF00FF00FF00FFULL;
            unsigned long long B1b = (Bb >> 8) & 0x00FF00FF00FF00FFULL;
            A0a += __shfl_xor_sync(0xffffffffu, A0a, 16);
            A1a += __shfl_xor_sync(0xffffffffu, A1a, 16);
            B0a += __shfl_xor_sync(0xffffffffu, B0a, 16);
            B1a += __shfl_xor_sync(0xffffffffu, B1a, 16);
            A0b += __shfl_xor_sync(0xffffffffu, A0b, 16);
            A1b += __shfl_xor_sync(0xffffffffu, A1b, 16);
            B0b += __shfl_xor_sync(0xffffffffu, B0b, 16);
            B1b += __shfl_xor_sync(0xffffffffu, B1b, 16);

            // entropy: every lane takes bin (lane&15); 4-round half-warp reduction
            const int bn = lane & 15;
            const int hwsh = (bn >> 2) * 16;
            float ent0, ent1;
            {
                unsigned long long w0 = (bn & 1) ? ((bn & 2) ? B1a : B0a)
                                                 : ((bn & 2) ? A1a : A0a);
                unsigned long long w1 = (bn & 1) ? ((bn & 2) ? B1b : B0b)
                                                 : ((bn & 2) ? A1b : A0b);
                float p0 = (float)((unsigned)(w0 >> hwsh) & 0xFFFFu) * invPr;
                float p1 = (float)((unsigned)(w1 >> hwsh) & 0xFFFFu) * invPr;
                ent0 = -p0 * __logf(p0 + 1e-9f);
                ent1 = -p1 * __logf(p1 + 1e-9f);
            }
            #pragma unroll
            for (int o = 1; o <= 8; o <<= 1) {
                ent0 += __shfl_xor_sync(0xffffffffu, ent0, o);
                ent1 += __shfl_xor_sync(0xffffffffu, ent1, o);
            }

            // fc1 + relu, both locations
            float ss0[5] = {mu0, sg0, gm0, kp0, ent0};
            float ss1[5] = {mu1, sg1, gm1, kp1, ent1};
            float h00 = b1, h01 = b1b, h10 = b1, h11 = b1b;
            #pragma unroll
            for (int k = 0; k < 5; k++) {
                h00 += w1c[k]  * ss0[k];
                h01 += w1c2[k] * ss0[k];
                h10 += w1c[k]  * ss1[k];
                h11 += w1c2[k] * ss1[k];
            }
            sh_h[l0 * 64 + lane]      = fmaxf(h00, 0.f);
            sh_h[l0 * 64 + lane + 32] = fmaxf(h01, 0.f);
            sh_h[l1 * 64 + lane]      = fmaxf(h10, 0.f);
            sh_h[l1 * 64 + lane + 32] = fmaxf(h11, 0.f);
            if (lane == 0) { sh_pb[l0] = pba; sh_pb[l1] = pbb; }
        }
    }
    __syncthreads();

    const int gr = lane >> 2, gc = lane & 3;
    const int r0 = warp * 16 + gr;              // valid for warp < 6

    // ---------------- phase 2: phi GEMM on tensor cores (warps 0..5) + proj ----------
    if (warp < 6) {
        float d[8][4];
        #pragma unroll
        for (int nt = 0; nt < 8; nt++)
            #pragma unroll
            for (int q = 0; q < 4; q++) d[nt][q] = 0.f;

        const int jc0 = 2 * gc, jc2 = 2 * gc + 8;
        for (int ks = 0; ks < 18; ks++) {
            const int jb = ks * 16;
            const int f0 = sh_f[jb + jc0], f1 = sh_f[jb + jc0 + 1];
            const int f2 = sh_f[jb + jc2], f3 = sh_f[jb + jc2 + 1];
            float v00 = sh_x[f0 + r0],     v01 = sh_x[f1 + r0];
            float v10 = sh_x[f0 + r0 + 8], v11 = sh_x[f1 + r0 + 8];
            float v20 = sh_x[f2 + r0],     v21 = sh_x[f3 + r0];
            float v30 = sh_x[f2 + r0 + 8], v31 = sh_x[f3 + r0 + 8];
            unsigned ah0 = bpack(v00, v01);
            unsigned ah1 = bpack(v10, v11);
            unsigned ah2 = bpack(v20, v21);
            unsigned ah3 = bpack(v30, v31);
            unsigned al0 = bpack(v00 - bf16val(v00), v01 - bf16val(v01));
            unsigned al1 = bpack(v10 - bf16val(v10), v11 - bf16val(v11));
            unsigned al2 = bpack(v20 - bf16val(v20), v21 - bf16val(v21));
            unsigned al3 = bpack(v30 - bf16val(v30), v31 - bf16val(v31));
            #pragma unroll
            for (int nt = 0; nt < 8; nt++) {
                const uint4 bf = __ldg(&g_Bf[(ks * 8 + nt) * 32 + lane]);
                mma_bf16(d[nt], ah0, ah1, ah2, ah3, bf.x, bf.y);
                mma_bf16(d[nt], ah0, ah1, ah2, ah3, bf.z, bf.w);
                mma_bf16(d[nt], al0, al1, al2, al3, bf.x, bf.y);
            }
        }

        float pr0 = 0.f, pr1 = 0.f;
        #pragma unroll
        for (int nt = 0; nt < 8; nt++) {
            const float2 h0v = *(const float2*)(sh_h + r0 * 64 + nt * 8 + 2 * gc);
            const float2 h1v = *(const float2*)(sh_h + (r0 + 8) * 64 + nt * 8 + 2 * gc);
            pr0 += d[nt][0] * h0v.x + d[nt][1] * h0v.y;
            pr1 += d[nt][2] * h1v.x + d[nt][3] * h1v.y;
        }
        pr0 += __shfl_xor_sync(0xffffffffu, pr0, 1);
        pr0 += __shfl_xor_sync(0xffffffffu, pr0, 2);
        pr1 += __shfl_xor_sync(0xffffffffu, pr1, 1);
        pr1 += __shfl_xor_sync(0xffffffffu, pr1, 2);
        if (gc == 0) {
            sh_proj[r0]     = pr0 + sh_pb[r0];
            sh_proj[r0 + 8] = pr1 + sh_pb[r0 + 8];
        }
    }
    __syncthreads();   // proj visible; all sh_x reads retired before sh_out alias writes

    // ---------------- phase 3: alpha GEMM on tensor cores (warps 0..5) + BN/SiLU -----
    if (warp < 6) {
        float d2[8][4];
        #pragma unroll
        for (int nt = 0; nt < 8; nt++)
            #pragma unroll
            for (int q = 0; q < 4; q++) d2[nt][q] = 0.f;

        #pragma unroll
        for (int ks = 0; ks < 4; ks++) {
            const float2* hr0 = (const float2*)(sh_h + r0 * 64 + ks * 16);
            const float2* hr1 = (const float2*)(sh_h + (r0 + 8) * 64 + ks * 16);
            float2 p00 = hr0[gc], p01 = hr0[gc + 4];
            float2 p10 = hr1[gc], p11 = hr1[gc + 4];
            unsigned ah0 = bpack(p00.x, p00.y);
            unsigned ah1 = bpack(p10.x, p10.y);
            unsigned ah2 = bpack(p01.x, p01.y);
            unsigned ah3 = bpack(p11.x, p11.y);
            unsigned al0 = bpack(p00.x - bf16val(p00.x), p00.y - bf16val(p00.y));
            unsigned al1 = bpack(p10.x - bf16val(p10.x), p10.y - bf16val(p10.y));
            unsigned al2 = bpack(p01.x - bf16val(p01.x), p01.y - bf16val(p01.y));
            unsigned al3 = bpack(p11.x - bf16val(p11.x), p11.y - bf16val(p11.y));
            #pragma unroll
            for (int nt = 0; nt < 8; nt++) {
                const uint4 bf = __ldg(&g_Af[(ks * 8 + nt) * 32 + lane]);
                mma_bf16(d2[nt], ah0, ah1, ah2, ah3, bf.x, bf.y);
                mma_bf16(d2[nt], ah0, ah1, ah2, ah3, bf.z, bf.w);
                mma_bf16(d2[nt], al0, al1, al2, al3, bf.x, bf.y);
            }
        }

        const float pj0 = sh_proj[r0];
        const float pj1 = sh_proj[r0 + 8];
        #pragma unroll
        for (int nt = 0; nt < 8; nt++) {
            const int c2 = nt * 8 + 2 * gc;
            const float4 bn0 = __ldg(&g_bn[c2]);       // {inv, mean, beta, alpha_b}
            const float4 bn1 = __ldg(&g_bn[c2 + 1]);
            float y00 = ((d2[nt][0] + bn0.w) * pj0 - bn0.y) * bn0.x + bn0.z;
            float y01 = ((d2[nt][1] + bn1.w) * pj0 - bn1.y) * bn1.x + bn1.z;
            float y10 = ((d2[nt][2] + bn0.w) * pj1 - bn0.y) * bn0.x + bn0.z;
            float y11 = ((d2[nt][3] + bn1.w) * pj1 - bn1.y) * bn1.x + bn1.z;
            sh_out[r0 * 65 + c2]           = y00 / (1.0f + __expf(-y00));
            sh_out[r0 * 65 + c2 + 1]       = y01 / (1.0f + __expf(-y01));
            sh_out[(r0 + 8) * 65 + c2]     = y10 / (1.0f + __expf(-y10));
            sh_out[(r0 + 8) * 65 + c2 + 1] = y11 / (1.0f + __expf(-y11));
        }
    }
    __syncthreads();

    // ---------------- phase 4: coalesced global write ----------------
    float* ob = out + (size_t)b * 64 * 9216 + y * 96;
    for (int i = tid; i < 6144; i += TPB) {
        int c2 = i / 96;
        int xx = i - c2 * 96;
        ob[(size_t)c2 * 9216 + xx] = sh_out[xx * 65 + c2];
    }
}

extern "C" void kernel_launch(void* const* d_in, const int* in_sizes, int n_in,
                              void* d_out, int out_size) {
    int ix = -1, ifc1w = -1, iaw = -1, ipw = -1, ipb = -1;
    int idx64[8]; int n64 = 0;
    for (int i = 0; i < n_in; i++) {
        switch (in_sizes[i]) {
            case 1179648: ix    = i; break;
            case 18432:   ipw   = i; break;
            case 4096:    iaw   = i; break;
            case 320:     ifc1w = i; break;
            case 288:     ipb   = i; break;
            case 64:      if (n64 < 8) idx64[n64++] = i; break;
            default: break;
        }
    }
    int ifc1b, iab, ibg, ibb, ibm, ibv;
    if (ix < 0 || ipw < 0 || iaw < 0 || ifc1w < 0 || ipb < 0 || n64 < 6) {
        ix = 0; ifc1w = 1; ifc1b = 2; iaw = 3; iab = 4; ipw = 5; ipb = 6;
        ibg = 7; ibb = 8; ibm = 9; ibv = 10;
    } else if (ix == 0) {
        ifc1b = idx64[0]; iab = idx64[1]; ibg = idx64[2];
        ibb   = idx64[3]; ibm = idx64[4]; ibv = idx64[5];
    } else {
        iab   = idx64[0]; ibb = idx64[1]; ibg = idx64[2];
        ibm   = idx64[3]; ibv = idx64[4]; ifc1b = idx64[5];
    }

    const float* x        = (const float*)d_in[ix];
    const float* fc1_w    = (const float*)d_in[ifc1w];
    const float* fc1_b    = (const float*)d_in[ifc1b];
    const float* alpha_w  = (const float*)d_in[iaw];
    const float* alpha_b  = (const float*)d_in[iab];
    const float* phi_w    = (const float*)d_in[ipw];
    const float* phi_b    = (const float*)d_in[ipb];
    const float* bn_gamma = (const float*)d_in[ibg];
    const float* bn_beta  = (const float*)d_in[ibb];
    const float* bn_mean  = (const float*)d_in[ibm];
    const float* bn_var   = (const float*)d_in[ibv];
    float* out = (float*)d_out;

    cudaFuncSetAttribute(sac_kernel, cudaFuncAttributeMaxDynamicSharedMemorySize, SMEM_BYTES);

    prep_kernel<<<18, 256>>>(alpha_w, phi_w, alpha_b, bn_gamma, bn_beta, bn_mean, bn_var);
    dim3 grid(96, 4);
    sac_kernel<<<grid, TPB, SMEM_BYTES>>>(x, fc1_w, fc1_b, phi_b, out);
}

// round 15
// speedup vs baseline: 1.4305x; 1.0554x over previous
#include <cuda_runtime.h>
#include <cuda_bf16.h>

#define TPB 256
#define NWARP 8

// Fragment-packed bf16-split B for phi MMA: (kstep 0..17, ntile 0..7, lane 0..31)
__device__ uint4 g_Bf[18 * 8 * 32];
// Fragment-packed bf16-split B for alpha MMA: (kstep 0..3, ntile 0..7, lane 0..31)
__device__ uint4 g_Af[4 * 8 * 32];
// Fused BN/alpha params per c2: {inv, mean, beta, alpha_b}
__device__ float4 g_bn[64];

__device__ __forceinline__ unsigned bpack(float lo, float hi) {
    __nv_bfloat162 t;
    t.x = __float2bfloat16(lo);
    t.y = __float2bfloat16(hi);
    return *reinterpret_cast<unsigned*>(&t);
}
__device__ __forceinline__ float bf16val(float v) {
    return __bfloat162float(__float2bfloat16(v));
}

// warp-wide integer reductions (sm_80+ redux.sync)
__device__ __forceinline__ unsigned redux_add(unsigned v) {
    unsigned r;
    asm("redux.sync.add.u32 %0, %1, 0xffffffff;" : "=r"(r) : "r"(v));
    return r;
}
__device__ __forceinline__ unsigned redux_min(unsigned v) {
    unsigned r;
    asm("redux.sync.min.u32 %0, %1, 0xffffffff;" : "=r"(r) : "r"(v));
    return r;
}
__device__ __forceinline__ unsigned redux_max(unsigned v) {
    unsigned r;
    asm("redux.sync.max.u32 %0, %1, 0xffffffff;" : "=r"(r) : "r"(v));
    return r;
}
// monotone float<->u32 order-preserving map (finite values)
__device__ __forceinline__ unsigned fkey(float f) {
    unsigned u = __float_as_uint(f);
    return ((int)u < 0) ? ~u : (u ^ 0x80000000u);
}
__device__ __forceinline__ float funkey(unsigned k) {
    unsigned u = ((int)k < 0) ? (k ^ 0x80000000u) : ~k;
    return __uint_as_float(u);
}

__global__ void prep_kernel(const float* __restrict__ aw, const float* __restrict__ pw,
                            const float* __restrict__ ab, const float* __restrict__ bg,
                            const float* __restrict__ bb, const float* __restrict__ bm,
                            const float* __restrict__ bv) {
    int i = blockIdx.x * blockDim.x + threadIdx.x;
    if (i < 4608) {   // phi B fragments: B[n=h][k=j] = pw[j*64+h]
        int ks  = i >> 8;
        int rem = i & 255;
        int nt  = rem >> 5, t = rem & 31;
        int n   = t >> 2, k0 = (t & 3) * 2;
        int h   = nt * 8 + n;
        int j   = ks * 16 + k0;
        float v0 = pw[j * 64 + h],       v1 = pw[(j + 1) * 64 + h];
        float v2 = pw[(j + 8) * 64 + h], v3 = pw[(j + 9) * 64 + h];
        g_Bf[i] = make_uint4(bpack(v0, v1), bpack(v2, v3),
                             bpack(v0 - bf16val(v0), v1 - bf16val(v1)),
                             bpack(v2 - bf16val(v2), v3 - bf16val(v3)));
    }
    if (i < 1024) {   // alpha B fragments: B[n=c2][k=h] = aw[c2*64+h]
        int ks  = i >> 8;
        int rem = i & 255;
        int nt  = rem >> 5, t = rem & 31;
        int n   = t >> 2, k0 = (t & 3) * 2;
        int c2  = nt * 8 + n;
        int h   = ks * 16 + k0;
        float v0 = aw[c2 * 64 + h],     v1 = aw[c2 * 64 + h + 1];
        float v2 = aw[c2 * 64 + h + 8], v3 = aw[c2 * 64 + h + 9];
        g_Af[i] = make_uint4(bpack(v0, v1), bpack(v2, v3),
                             bpack(v0 - bf16val(v0), v1 - bf16val(v1)),
                             bpack(v2 - bf16val(v2), v3 - bf16val(v3)));
    }
    if (i < 64) {
        float inv = bg[i] / sqrtf(bv[i] + 1e-5f);
        g_bn[i] = make_float4(inv, bm[i], bb[i], ab[i]);
    }
}

__device__ __forceinline__ void mma_bf16(float* d, unsigned a0, unsigned a1,
                                         unsigned a2, unsigned a3,
                                         unsigned b0, unsigned b1) {
    asm volatile(
        "mma.sync.aligned.m16n8k16.row.col.f32.bf16.bf16.f32 "
        "{%0,%1,%2,%3}, {%4,%5,%6,%7}, {%8,%9}, {%0,%1,%2,%3};"
        : "+f"(d[0]), "+f"(d[1]), "+f"(d[2]), "+f"(d[3])
        : "r"(a0), "r"(a1), "r"(a2), "r"(a3), "r"(b0), "r"(b1));
}

// Shared layout (floats):
//   [0      .. 9504)  sh_x   : 32 ch * 3 rows * 99 (stride 297)  -> aliased as sh_out (96*65)
//   [9504   .. 15648) sh_h   : 96 loc * 64 hidden
//   [15648  .. 15744) sh_proj: 96
//   [15744  .. 15840) sh_pb  : 96
//   [15840  .. 16128) sh_f   : 288 ints (j -> sh_x base offset)
#define SMEM_FLOATS 16128
#define SMEM_BYTES  (SMEM_FLOATS * 4)

__global__ __launch_bounds__(TPB, 3)
void sac_kernel(const float* __restrict__ x,
                const float* __restrict__ fc1_w, const float* __restrict__ fc1_b,
                const float* __restrict__ phi_b,
                float* __restrict__ out)
{
    extern __shared__ float smem[];
    float* sh_x    = smem;
    float* sh_h    = smem + 9504;
    float* sh_proj = smem + 15648;
    float* sh_pb   = smem + 15744;
    int*   sh_f    = (int*)(smem + 15840);
    float* sh_out  = smem;   // aliases sh_x after phi MMA (guarded by __syncthreads)

    const int y    = blockIdx.x;
    const int b    = blockIdx.y;
    const int tid  = threadIdx.x;
    const int warp = tid >> 5;
    const int lane = tid & 31;

    // ---------------- phase 0: stage x rows + build f-table ----------------
    const float* xb = x + (size_t)b * 32 * 9216;
    for (int i = tid; i < 32 * 3 * 98; i += TPB) {
        int c = i / 294, rem = i - c * 294;
        int r = rem / 98, cc = rem - r * 98;
        int gy = y + r - 1, gx = cc - 1;
        float v = 0.f;
        if ((unsigned)gy < 96u && (unsigned)gx < 96u)
            v = xb[(c * 96 + gy) * 96 + gx];
        sh_x[c * 297 + r * 99 + cc] = v;
    }
    for (int i = tid; i < 288; i += TPB) {
        int c = i / 9, rm = i % 9;
        sh_f[i] = c * 297 + (rm / 3) * 99 + (rm % 3);
    }
    __syncthreads();

    // ---------------- phase 1: stats + fc1, two locations per iter, REDUX ----------------
    const float inv288 = 1.0f / 288.0f;
    const float invPr  = 1.0f / (288.0f + 1e-6f);

    {
        float pbw[9];
        #pragma unroll
        for (int k = 0; k < 9; k++) pbw[k] = __ldg(&phi_b[lane * 9 + k]);
        float w1c[5], w1c2[5];
        #pragma unroll
        for (int k = 0; k < 5; k++) {
            w1c[k]  = __ldg(&fc1_w[lane * 5 + k]);
            w1c2[k] = __ldg(&fc1_w[(lane + 32) * 5 + k]);
        }
        const float b1  = __ldg(&fc1_b[lane]);
        const float b1b = __ldg(&fc1_b[lane + 32]);

        #pragma unroll 1
        for (int t = 0; t < 6; t++) {
            const int l0 = t * 8 + warp;     // 0..47
            const int l1 = l0 + 48;          // 48..95
            const float* base0 = sh_x + lane * 297 + l0;
            const float* base1 = sh_x + lane * 297 + l1;

            float S1a = 0.f, S2a = 0.f, S3a = 0.f, S4a = 0.f, pba = 0.f, mna, mxa;
            float S1b = 0.f, S2b = 0.f, S3b = 0.f, S4b = 0.f, pbb = 0.f, mnb, mxb;
            {
                float v[9];
                #pragma unroll
                for (int r = 0; r < 3; r++)
                    #pragma unroll
                    for (int kc = 0; kc < 3; kc++)
                        v[r * 3 + kc] = base0[r * 99 + kc];
                mna = v[0]; mxa = v[0];
                #pragma unroll
                for (int k = 0; k < 9; k++) {
                    float vk = v[k], v2 = vk * vk;
                    S1a += vk; S2a += v2; S3a += v2 * vk; S4a += v2 * v2;
                    mna = fminf(mna, vk); mxa = fmaxf(mxa, vk);
                    pba += pbw[k] * vk;
                }
            }
            {
                float v[9];
                #pragma unroll
                for (int r = 0; r < 3; r++)
                    #pragma unroll
                    for (int kc = 0; kc < 3; kc++)
                        v[r * 3 + kc] = base1[r * 99 + kc];
                mnb = v[0]; mxb = v[0];
                #pragma unroll
                for (int k = 0; k < 9; k++) {
                    float vk = v[k], v2 = vk * vk;
                    S1b += vk; S2b += v2; S3b += v2 * vk; S4b += v2 * v2;
                    mnb = fminf(mnb, vk); mxb = fmaxf(mxb, vk);
                    pbb += pbw[k] * vk;
                }
            }

            // min/max via single-instruction warp reductions (order-preserving key map)
            mna = funkey(redux_min(fkey(mna)));
            mxa = funkey(redux_max(fkey(mxa)));
            mnb = funkey(redux_min(fkey(mnb)));
            mxb = funkey(redux_max(fkey(mxb)));

            // histogram: nibble counters; bins {q,q+4,q+8,q+12} are halfword-aligned
            unsigned long long nib0 = 0ULL, nib1 = 0ULL;
            {
                float den0 = (mxa - mna) + 1e-6f;
                #pragma unroll
                for (int r = 0; r < 3; r++)
                    #pragma unroll
                    for (int kc = 0; kc < 3; kc++) {
                        float pn = (base0[r * 99 + kc] - mna) / den0;
                        int bi = (int)(pn * 15.0f);
                        bi = max(0, min(15, bi));
                        nib0 += 1ULL << (bi * 4);
                    }
                float den1 = (mxb - mnb) + 1e-6f;
                #pragma unroll
                for (int r = 0; r < 3; r++)
                    #pragma unroll
                    for (int kc = 0; kc < 3; kc++) {
                        float pn = (base1[r * 99 + kc] - mnb) / den1;
                        int bi = (int)(pn * 15.0f);
                        bi = max(0, min(15, bi));
                        nib1 += 1ULL << (bi * 4);
                    }
            }
            const unsigned long long HM = 0x000F000F000F000FULL;
            unsigned long long h0a =  nib0        & HM;   // bins 0,4,8,12
            unsigned long long h1a = (nib0 >> 4)  & HM;   // bins 1,5,9,13
            unsigned long long h2a = (nib0 >> 8)  & HM;   // bins 2,6,10,14
            unsigned long long h3a = (nib0 >> 12) & HM;   // bins 3,7,11,15
            unsigned long long h0b =  nib1        & HM;
            unsigned long long h1b = (nib1 >> 4)  & HM;
            unsigned long long h2b = (nib1 >> 8)  & HM;
            unsigned long long h3b = (nib1 >> 12) & HM;
            // 8 redux per location: halfword-packed warp sums, broadcast to all lanes
            unsigned ra0 = redux_add((unsigned)h0a), ra1 = redux_add((unsigned)(h0a >> 32));
            unsigned ra2 = redux_add((unsigned)h1a), ra3 = redux_add((unsigned)(h1a >> 32));
            unsigned ra4 = redux_add((unsigned)h2a), ra5 = redux_add((unsigned)(h2a >> 32));
            unsigned ra6 = redux_add((unsigned)h3a), ra7 = redux_add((unsigned)(h3a >> 32));
            unsigned rb0 = redux_add((unsigned)h0b), rb1 = redux_add((unsigned)(h0b >> 32));
            unsigned rb2 = redux_add((unsigned)h1b), rb3 = redux_add((unsigned)(h1b >> 32));
            unsigned rb4 = redux_add((unsigned)h2b), rb5 = redux_add((unsigned)(h2b >> 32));
            unsigned rb6 = redux_add((unsigned)h3b), rb7 = redux_add((unsigned)(h3b >> 32));

            // moments butterfly (10 fp32 values; independent of redux stream)
            #pragma unroll
            for (int o = 16; o; o >>= 1) {
                S1a += __shfl_xor_sync(0xffffffffu, S1a, o);
                S2a += __shfl_xor_sync(0xffffffffu, S2a, o);
                S3a += __shfl_xor_sync(0xffffffffu, S3a, o);
                S4a += __shfl_xor_sync(0xffffffffu, S4a, o);
                pba += __shfl_xor_sync(0xffffffffu, pba, o);
                S1b += __shfl_xor_sync(0xffffffffu, S1b, o);
                S2b += __shfl_xor_sync(0xffffffffu, S2b, o);
                S3b += __shfl_xor_sync(0xffffffffu, S3b, o);
                S4b += __shfl_xor_sync(0xffffffffu, S4b, o);
                pbb += __shfl_xor_sync(0xffffffffu, pbb, o);
            }

            // entropy: lane handles bin (lane&15); counts already warp-summed
            const int bn  = lane & 15;
            const int q   = bn & 3;
            const int idx = bn >> 2;            // 0..3
            const int sh  = (idx & 1) * 16;
            unsigned selA = (q == 0) ? ((idx < 2) ? ra0 : ra1)
                          : (q == 1) ? ((idx < 2) ? ra2 : ra3)
                          : (q == 2) ? ((idx < 2) ? ra4 : ra5)
                                     : ((idx < 2) ? ra6 : ra7);
            unsigned selB = (q == 0) ? ((idx < 2) ? rb0 : rb1)
                          : (q == 1) ? ((idx < 2) ? rb2 : rb3)
                          : (q == 2) ? ((idx < 2) ? rb4 : rb5)
                                     : ((idx < 2) ? rb6 : rb7);
            float p0 = (float)((selA >> sh) & 0xFFFFu) * invPr;
            float p1 = (float)((selB >> sh) & 0xFFFFu) * invPr;
            float ent0 = -p0 * __logf(p0 + 1e-9f);
            float ent1 = -p1 * __logf(p1 + 1e-9f);
            #pragma unroll
            for (int o = 1; o <= 8; o <<= 1) {
                ent0 += __shfl_xor_sync(0xffffffffu, ent0, o);
                ent1 += __shfl_xor_sync(0xffffffffu, ent1, o);
            }

            // moments -> stats, both locations
            float mu0 = S1a * inv288, mu1 = S1b * inv288;
            float r20 = S2a * inv288, r30 = S3a * inv288, r40 = S4a * inv288;
            float r21 = S2b * inv288, r31 = S3b * inv288, r41 = S4b * inv288;
            float mu20 = mu0 * mu0, mu21 = mu1 * mu1;
            float m20 = r20 - mu20, m21v = r21 - mu21;
            float m30 = r30 - mu0 * (3.0f * r20 - 2.0f * mu20);
            float m31 = r31 - mu1 * (3.0f * r21 - 2.0f * mu21);
            float m40 = r40 - mu0 * (4.0f * r30 - mu0 * (6.0f * r20 - 3.0f * mu20));
            float m41 = r41 - mu1 * (4.0f * r31 - mu1 * (6.0f * r21 - 3.0f * mu21));
            float sg0 = sqrtf(m20 + 1e-6f), sg1 = sqrtf(m21v + 1e-6f);
            float iq0 = 1.0f / (sg0 + 1e-6f), iq1 = 1.0f / (sg1 + 1e-6f);
            float iq20 = iq0 * iq0, iq21 = iq1 * iq1;
            float gm0 = m30 * iq20 * iq0, gm1 = m31 * iq21 * iq1;
            float kp0 = m40 * iq20 * iq20 - 3.0f, kp1 = m41 * iq21 * iq21 - 3.0f;

            // fc1 + relu, both locations
            float ss0[5] = {mu0, sg0, gm0, kp0, ent0};
            float ss1[5] = {mu1, sg1, gm1, kp1, ent1};
            float h00 = b1, h01 = b1b, h10 = b1, h11 = b1b;
            #pragma unroll
            for (int k = 0; k < 5; k++) {
                h00 += w1c[k]  * ss0[k];
                h01 += w1c2[k] * ss0[k];
                h10 += w1c[k]  * ss1[k];
                h11 += w1c2[k] * ss1[k];
            }
            sh_h[l0 * 64 + lane]      = fmaxf(h00, 0.f);
            sh_h[l0 * 64 + lane + 32] = fmaxf(h01, 0.f);
            sh_h[l1 * 64 + lane]      = fmaxf(h10, 0.f);
            sh_h[l1 * 64 + lane + 32] = fmaxf(h11, 0.f);
            if (lane == 0) { sh_pb[l0] = pba; sh_pb[l1] = pbb; }
        }
    }
    __syncthreads();

    const int gr = lane >> 2, gc = lane & 3;
    const int r0 = warp * 16 + gr;              // valid for warp < 6

    // ---------------- phase 2: phi GEMM on tensor cores (warps 0..5) + proj ----------
    if (warp < 6) {
        float d[8][4];
        #pragma unroll
        for (int nt = 0; nt < 8; nt++)
            #pragma unroll
            for (int q2 = 0; q2 < 4; q2++) d[nt][q2] = 0.f;

        const int jc0 = 2 * gc, jc2 = 2 * gc + 8;
        for (int ks = 0; ks < 18; ks++) {
            const int jb = ks * 16;
            const int f0 = sh_f[jb + jc0], f1 = sh_f[jb + jc0 + 1];
            const int f2 = sh_f[jb + jc2], f3 = sh_f[jb + jc2 + 1];
            float v00 = sh_x[f0 + r0],     v01 = sh_x[f1 + r0];
            float v10 = sh_x[f0 + r0 + 8], v11 = sh_x[f1 + r0 + 8];
            float v20 = sh_x[f2 + r0],     v21 = sh_x[f3 + r0];
            float v30 = sh_x[f2 + r0 + 8], v31 = sh_x[f3 + r0 + 8];
            unsigned ah0 = bpack(v00, v01);
            unsigned ah1 = bpack(v10, v11);
            unsigned ah2 = bpack(v20, v21);
            unsigned ah3 = bpack(v30, v31);
            unsigned al0 = bpack(v00 - bf16val(v00), v01 - bf16val(v01));
            unsigned al1 = bpack(v10 - bf16val(v10), v11 - bf16val(v11));
            unsigned al2 = bpack(v20 - bf16val(v20), v21 - bf16val(v21));
            unsigned al3 = bpack(v30 - bf16val(v30), v31 - bf16val(v31));
            #pragma unroll
            for (int nt = 0; nt < 8; nt++) {
                const uint4 bf = __ldg(&g_Bf[(ks * 8 + nt) * 32 + lane]);
                mma_bf16(d[nt], ah0, ah1, ah2, ah3, bf.x, bf.y);
                mma_bf16(d[nt], ah0, ah1, ah2, ah3, bf.z, bf.w);
                mma_bf16(d[nt], al0, al1, al2, al3, bf.x, bf.y);
            }
        }

        float pr0 = 0.f, pr1 = 0.f;
        #pragma unroll
        for (int nt = 0; nt < 8; nt++) {
            const float2 h0v = *(const float2*)(sh_h + r0 * 64 + nt * 8 + 2 * gc);
            const float2 h1v = *(const float2*)(sh_h + (r0 + 8) * 64 + nt * 8 + 2 * gc);
            pr0 += d[nt][0] * h0v.x + d[nt][1] * h0v.y;
            pr1 += d[nt][2] * h1v.x + d[nt][3] * h1v.y;
        }
        pr0 += __shfl_xor_sync(0xffffffffu, pr0, 1);
        pr0 += __shfl_xor_sync(0xffffffffu, pr0, 2);
        pr1 += __shfl_xor_sync(0xffffffffu, pr1, 1);
        pr1 += __shfl_xor_sync(0xffffffffu, pr1, 2);
        if (gc == 0) {
            sh_proj[r0]     = pr0 + sh_pb[r0];
            sh_proj[r0 + 8] = pr1 + sh_pb[r0 + 8];
        }
    }
    __syncthreads();   // proj visible; all sh_x reads retired before sh_out alias writes

    // ---------------- phase 3: alpha GEMM on tensor cores (warps 0..5) + BN/SiLU -----
    if (warp < 6) {
        float d2[8][4];
        #pragma unroll
        for (int nt = 0; nt < 8; nt++)
            #pragma unroll
            for (int q2 = 0; q2 < 4; q2++) d2[nt][q2] = 0.f;

        #pragma unroll
        for (int ks = 0; ks < 4; ks++) {
            const float2* hr0 = (const float2*)(sh_h + r0 * 64 + ks * 16);
            const float2* hr1 = (const float2*)(sh_h + (r0 + 8) * 64 + ks * 16);
            float2 p00 = hr0[gc], p01 = hr0[gc + 4];
            float2 p10 = hr1[gc], p11 = hr1[gc + 4];
            unsigned ah0 = bpack(p00.x, p00.y);
            unsigned ah1 = bpack(p10.x, p10.y);
            unsigned ah2 = bpack(p01.x, p01.y);
            unsigned ah3 = bpack(p11.x, p11.y);
            unsigned al0 = bpack(p00.x - bf16val(p00.x), p00.y - bf16val(p00.y));
            unsigned al1 = bpack(p10.x - bf16val(p10.x), p10.y - bf16val(p10.y));
            unsigned al2 = bpack(p01.x - bf16val(p01.x), p01.y - bf16val(p01.y));
            unsigned al3 = bpack(p11.x - bf16val(p11.x), p11.y - bf16val(p11.y));
            #pragma unroll
            for (int nt = 0; nt < 8; nt++) {
                const uint4 bf = __ldg(&g_Af[(ks * 8 + nt) * 32 + lane]);
                mma_bf16(d2[nt], ah0, ah1, ah2, ah3, bf.x, bf.y);
                mma_bf16(d2[nt], ah0, ah1, ah2, ah3, bf.z, bf.w);
                mma_bf16(d2[nt], al0, al1, al2, al3, bf.x, bf.y);
            }
        }

        const float pj0 = sh_proj[r0];
        const float pj1 = sh_proj[r0 + 8];
        #pragma unroll
        for (int nt = 0; nt < 8; nt++) {
            const int c2 = nt * 8 + 2 * gc;
            const float4 bn0 = __ldg(&g_bn[c2]);       // {inv, mean, beta, alpha_b}
            const float4 bn1 = __ldg(&g_bn[c2 + 1]);
            float y00 = ((d2[nt][0] + bn0.w) * pj0 - bn0.y) * bn0.x + bn0.z;
            float y01 = ((d2[nt][1] + bn1.w) * pj0 - bn1.y) * bn1.x + bn1.z;
            float y10 = ((d2[nt][2] + bn0.w) * pj1 - bn0.y) * bn0.x + bn0.z;
            float y11 = ((d2[nt][3] + bn1.w) * pj1 - bn1.y) * bn1.x + bn1.z;
            sh_out[r0 * 65 + c2]           = y00 / (1.0f + __expf(-y00));
            sh_out[r0 * 65 + c2 + 1]       = y01 / (1.0f + __expf(-y01));
            sh_out[(r0 + 8) * 65 + c2]     = y10 / (1.0f + __expf(-y10));
            sh_out[(r0 + 8) * 65 + c2 + 1] = y11 / (1.0f + __expf(-y11));
        }
    }
    __syncthreads();

    // ---------------- phase 4: coalesced global write ----------------
    float* ob = out + (size_t)b * 64 * 9216 + y * 96;
    for (int i = tid; i < 6144; i += TPB) {
        int c2 = i / 96;
        int xx = i - c2 * 96;
        ob[(size_t)c2 * 9216 + xx] = sh_out[xx * 65 + c2];
    }
}

extern "C" void kernel_launch(void* const* d_in, const int* in_sizes, int n_in,
                              void* d_out, int out_size) {
    int ix = -1, ifc1w = -1, iaw = -1, ipw = -1, ipb = -1;
    int idx64[8]; int n64 = 0;
    for (int i = 0; i < n_in; i++) {
        switch (in_sizes[i]) {
            case 1179648: ix    = i; break;
            case 18432:   ipw   = i; break;
            case 4096:    iaw   = i; break;
            case 320:     ifc1w = i; break;
            case 288:     ipb   = i; break;
            case 64:      if (n64 < 8) idx64[n64++] = i; break;
            default: break;
        }
    }
    int ifc1b, iab, ibg, ibb, ibm, ibv;
    if (ix < 0 || ipw < 0 || iaw < 0 || ifc1w < 0 || ipb < 0 || n64 < 6) {
        ix = 0; ifc1w = 1; ifc1b = 2; iaw = 3; iab = 4; ipw = 5; ipb = 6;
        ibg = 7; ibb = 8; ibm = 9; ibv = 10;
    } else if (ix == 0) {
        ifc1b = idx64[0]; iab = idx64[1]; ibg = idx64[2];
        ibb   = idx64[3]; ibm = idx64[4]; ibv = idx64[5];
    } else {
        iab   = idx64[0]; ibb = idx64[1]; ibg = idx64[2];
        ibm   = idx64[3]; ibv = idx64[4]; ifc1b = idx64[5];
    }

    const float* x        = (const float*)d_in[ix];
    const float* fc1_w    = (const float*)d_in[ifc1w];
    const float* fc1_b    = (const float*)d_in[ifc1b];
    const float* alpha_w  = (const float*)d_in[iaw];
    const float* alpha_b  = (const float*)d_in[iab];
    const float* phi_w    = (const float*)d_in[ipw];
    const float* phi_b    = (const float*)d_in[ipb];
    const float* bn_gamma = (const float*)d_in[ibg];
    const float* bn_beta  = (const float*)d_in[ibb];
    const float* bn_mean  = (const float*)d_in[ibm];
    const float* bn_var   = (const float*)d_in[ibv];
    float* out = (float*)d_out;

    cudaFuncSetAttribute(sac_kernel, cudaFuncAttributeMaxDynamicSharedMemorySize, SMEM_BYTES);

    prep_kernel<<<18, 256>>>(alpha_w, phi_w, alpha_b, bn_gamma, bn_beta, bn_mean, bn_var);
    dim3 grid(96, 4);
    sac_kernel<<<grid, TPB, SMEM_BYTES>>>(x, fc1_w, fc1_b, phi_b, out);
}

// round 16
// speedup vs baseline: 1.4312x; 1.0005x over previous
#include <cuda_runtime.h>
#include <cuda_bf16.h>

#define TPB 256
#define NWARP 8

// Fragment-packed bf16-split B for phi MMA: (kstep 0..17, ntile 0..8, lane 0..31)
// nt==8 carries phi_b in n-row 0 (t_pb column), rows 1..7 zero.
__device__ uint4 g_Bf[18 * 9 * 32];
// Fragment-packed bf16-split B for alpha MMA: (kstep 0..3, ntile 0..7, lane 0..31)
__device__ uint4 g_Af[4 * 8 * 32];
// Fused BN/alpha params per c2: {inv, mean, beta, alpha_b}
__device__ float4 g_bn[64];

__device__ __forceinline__ unsigned bpack(float lo, float hi) {
    __nv_bfloat162 t;
    t.x = __float2bfloat16(lo);
    t.y = __float2bfloat16(hi);
    return *reinterpret_cast<unsigned*>(&t);
}
__device__ __forceinline__ float bf16val(float v) {
    return __bfloat162float(__float2bfloat16(v));
}

// warp-wide integer reductions (sm_80+ redux.sync)
__device__ __forceinline__ unsigned redux_add(unsigned v) {
    unsigned r;
    asm("redux.sync.add.u32 %0, %1, 0xffffffff;" : "=r"(r) : "r"(v));
    return r;
}
__device__ __forceinline__ unsigned redux_min(unsigned v) {
    unsigned r;
    asm("redux.sync.min.u32 %0, %1, 0xffffffff;" : "=r"(r) : "r"(v));
    return r;
}
__device__ __forceinline__ unsigned redux_max(unsigned v) {
    unsigned r;
    asm("redux.sync.max.u32 %0, %1, 0xffffffff;" : "=r"(r) : "r"(v));
    return r;
}
__device__ __forceinline__ unsigned fkey(float f) {
    unsigned u = __float_as_uint(f);
    return ((int)u < 0) ? ~u : (u ^ 0x80000000u);
}
__device__ __forceinline__ float funkey(unsigned k) {
    unsigned u = ((int)k < 0) ? (k ^ 0x80000000u) : ~k;
    return __uint_as_float(u);
}

__global__ void prep_kernel(const float* __restrict__ aw, const float* __restrict__ pw,
                            const float* __restrict__ pb,
                            const float* __restrict__ ab, const float* __restrict__ bg,
                            const float* __restrict__ bb, const float* __restrict__ bm,
                            const float* __restrict__ bv) {
    int i = blockIdx.x * blockDim.x + threadIdx.x;
    if (i < 18 * 9 * 32) {   // phi B fragments incl. nt=8 (phi_b column)
        int ks  = i / 288;
        int rem = i % 288;
        int nt  = rem >> 5, t = rem & 31;
        int n   = t >> 2, k0 = (t & 3) * 2;
        int j   = ks * 16 + k0;
        float v0, v1, v2, v3;
        if (nt < 8) {
            int h = nt * 8 + n;
            v0 = pw[j * 64 + h];       v1 = pw[(j + 1) * 64 + h];
            v2 = pw[(j + 8) * 64 + h]; v3 = pw[(j + 9) * 64 + h];
        } else if (n == 0) {
            v0 = pb[j];     v1 = pb[j + 1];
            v2 = pb[j + 8]; v3 = pb[j + 9];
        } else {
            v0 = v1 = v2 = v3 = 0.f;
        }
        g_Bf[i] = make_uint4(bpack(v0, v1), bpack(v2, v3),
                             bpack(v0 - bf16val(v0), v1 - bf16val(v1)),
                             bpack(v2 - bf16val(v2), v3 - bf16val(v3)));
    }
    if (i < 1024) {   // alpha B fragments: B[n=c2][k=h] = aw[c2*64+h]
        int ks  = i >> 8;
        int rem = i & 255;
        int nt  = rem >> 5, t = rem & 31;
        int n   = t >> 2, k0 = (t & 3) * 2;
        int c2  = nt * 8 + n;
        int h   = ks * 16 + k0;
        float v0 = aw[c2 * 64 + h],     v1 = aw[c2 * 64 + h + 1];
        float v2 = aw[c2 * 64 + h + 8], v3 = aw[c2 * 64 + h + 9];
        g_Af[i] = make_uint4(bpack(v0, v1), bpack(v2, v3),
                             bpack(v0 - bf16val(v0), v1 - bf16val(v1)),
                             bpack(v2 - bf16val(v2), v3 - bf16val(v3)));
    }
    if (i < 64) {
        float inv = bg[i] / sqrtf(bv[i] + 1e-5f);
        g_bn[i] = make_float4(inv, bm[i], bb[i], ab[i]);
    }
}

__device__ __forceinline__ void mma_bf16(float* d, unsigned a0, unsigned a1,
                                         unsigned a2, unsigned a3,
                                         unsigned b0, unsigned b1) {
    asm volatile(
        "mma.sync.aligned.m16n8k16.row.col.f32.bf16.bf16.f32 "
        "{%0,%1,%2,%3}, {%4,%5,%6,%7}, {%8,%9}, {%0,%1,%2,%3};"
        : "+f"(d[0]), "+f"(d[1]), "+f"(d[2]), "+f"(d[3])
        : "r"(a0), "r"(a1), "r"(a2), "r"(a3), "r"(b0), "r"(b1));
}

// Shared layout (floats):
//   [0      .. 9504)  sh_x   : 32 ch * 3 rows * 99 (stride 297)
//   [9504   .. 15648) sh_h   : 96 loc * 64 hidden
//   [15648  .. 15744) sh_proj: 96
//   [15744  .. 16032) sh_f   : 288 ints (j -> sh_x base offset)
#define SMEM_FLOATS 16032
#define SMEM_BYTES  (SMEM_FLOATS * 4)

__global__ __launch_bounds__(TPB, 3)
void sac_kernel(const float* __restrict__ x,
                const float* __restrict__ fc1_w, const float* __restrict__ fc1_b,
                float* __restrict__ out)
{
    extern __shared__ float smem[];
    float* sh_x    = smem;
    float* sh_h    = smem + 9504;
    float* sh_proj = smem + 15648;
    int*   sh_f    = (int*)(smem + 15744);

    const int y    = blockIdx.x;
    const int b    = blockIdx.y;
    const int tid  = threadIdx.x;
    const int warp = tid >> 5;
    const int lane = tid & 31;

    // ---------------- phase 0: stage x rows + build f-table ----------------
    const float* xb = x + (size_t)b * 32 * 9216;
    for (int i = tid; i < 32 * 3 * 98; i += TPB) {
        int c = i / 294, rem = i - c * 294;
        int r = rem / 98, cc = rem - r * 98;
        int gy = y + r - 1, gx = cc - 1;
        float v = 0.f;
        if ((unsigned)gy < 96u && (unsigned)gx < 96u)
            v = xb[(c * 96 + gy) * 96 + gx];
        sh_x[c * 297 + r * 99 + cc] = v;
    }
    for (int i = tid; i < 288; i += TPB) {
        int c = i / 9, rm = i % 9;
        sh_f[i] = c * 297 + (rm / 3) * 99 + (rm % 3);
    }
    __syncthreads();

    // ---------------- phase 1: stats + fc1, two locations per iter ----------------
    const float inv288 = 1.0f / 288.0f;
    const float invPr  = 1.0f / (288.0f + 1e-6f);

    {
        float w1c[5], w1c2[5];
        #pragma unroll
        for (int k = 0; k < 5; k++) {
            w1c[k]  = __ldg(&fc1_w[lane * 5 + k]);
            w1c2[k] = __ldg(&fc1_w[(lane + 32) * 5 + k]);
        }
        const float b1  = __ldg(&fc1_b[lane]);
        const float b1b = __ldg(&fc1_b[lane + 32]);

        #pragma unroll 1
        for (int t = 0; t < 6; t++) {
            const int l0 = t * 8 + warp;     // 0..47
            const int l1 = l0 + 48;          // 48..95
            const float* base0 = sh_x + lane * 297 + l0;
            const float* base1 = sh_x + lane * 297 + l1;

            float S1a = 0.f, S2a = 0.f, S3a = 0.f, S4a = 0.f, mna, mxa;
            float S1b = 0.f, S2b = 0.f, S3b = 0.f, S4b = 0.f, mnb, mxb;
            {
                float v[9];
                #pragma unroll
                for (int r = 0; r < 3; r++)
                    #pragma unroll
                    for (int kc = 0; kc < 3; kc++)
                        v[r * 3 + kc] = base0[r * 99 + kc];
                mna = v[0]; mxa = v[0];
                #pragma unroll
                for (int k = 0; k < 9; k++) {
                    float vk = v[k], v2 = vk * vk;
                    S1a += vk; S2a += v2; S3a += v2 * vk; S4a += v2 * v2;
                    mna = fminf(mna, vk); mxa = fmaxf(mxa, vk);
                }
            }
            {
                float v[9];
                #pragma unroll
                for (int r = 0; r < 3; r++)
                    #pragma unroll
                    for (int kc = 0; kc < 3; kc++)
                        v[r * 3 + kc] = base1[r * 99 + kc];
                mnb = v[0]; mxb = v[0];
                #pragma unroll
                for (int k = 0; k < 9; k++) {
                    float vk = v[k], v2 = vk * vk;
                    S1b += vk; S2b += v2; S3b += v2 * vk; S4b += v2 * v2;
                    mnb = fminf(mnb, vk); mxb = fmaxf(mxb, vk);
                }
            }

            // min/max via single-instruction warp reductions
            mna = funkey(redux_min(fkey(mna)));
            mxa = funkey(redux_max(fkey(mxa)));
            mnb = funkey(redux_min(fkey(mnb)));
            mxb = funkey(redux_max(fkey(mxb)));

            // histogram: nibble counters; bins {q,q+4,q+8,q+12} halfword-aligned
            unsigned long long nib0 = 0ULL, nib1 = 0ULL;
            {
                float den0 = (mxa - mna) + 1e-6f;
                #pragma unroll
                for (int r = 0; r < 3; r++)
                    #pragma unroll
                    for (int kc = 0; kc < 3; kc++) {
                        float pn = (base0[r * 99 + kc] - mna) / den0;
                        int bi = (int)(pn * 15.0f);
                        bi = max(0, min(15, bi));
                        nib0 += 1ULL << (bi * 4);
                    }
                float den1 = (mxb - mnb) + 1e-6f;
                #pragma unroll
                for (int r = 0; r < 3; r++)
                    #pragma unroll
                    for (int kc = 0; kc < 3; kc++) {
                        float pn = (base1[r * 99 + kc] - mnb) / den1;
                        int bi = (int)(pn * 15.0f);
                        bi = max(0, min(15, bi));
                        nib1 += 1ULL << (bi * 4);
                    }
            }
            const unsigned long long HM = 0x000F000F000F000FULL;
            unsigned long long h0a =  nib0        & HM;
            unsigned long long h1a = (nib0 >> 4)  & HM;
            unsigned long long h2a = (nib0 >> 8)  & HM;
            unsigned long long h3a = (nib0 >> 12) & HM;
            unsigned long long h0b =  nib1        & HM;
            unsigned long long h1b = (nib1 >> 4)  & HM;
            unsigned long long h2b = (nib1 >> 8)  & HM;
            unsigned long long h3b = (nib1 >> 12) & HM;
            unsigned ra0 = redux_add((unsigned)h0a), ra1 = redux_add((unsigned)(h0a >> 32));
            unsigned ra2 = redux_add((unsigned)h1a), ra3 = redux_add((unsigned)(h1a >> 32));
            unsigned ra4 = redux_add((unsigned)h2a), ra5 = redux_add((unsigned)(h2a >> 32));
            unsigned ra6 = redux_add((unsigned)h3a), ra7 = redux_add((unsigned)(h3a >> 32));
            unsigned rb0 = redux_add((unsigned)h0b), rb1 = redux_add((unsigned)(h0b >> 32));
            unsigned rb2 = redux_add((unsigned)h1b), rb3 = redux_add((unsigned)(h1b >> 32));
            unsigned rb4 = redux_add((unsigned)h2b), rb5 = redux_add((unsigned)(h2b >> 32));
            unsigned rb6 = redux_add((unsigned)h3b), rb7 = redux_add((unsigned)(h3b >> 32));

            // moments butterfly (8 fp32 values)
            #pragma unroll
            for (int o = 16; o; o >>= 1) {
                S1a += __shfl_xor_sync(0xffffffffu, S1a, o);
                S2a += __shfl_xor_sync(0xffffffffu, S2a, o);
                S3a += __shfl_xor_sync(0xffffffffu, S3a, o);
                S4a += __shfl_xor_sync(0xffffffffu, S4a, o);
                S1b += __shfl_xor_sync(0xffffffffu, S1b, o);
                S2b += __shfl_xor_sync(0xffffffffu, S2b, o);
                S3b += __shfl_xor_sync(0xffffffffu, S3b, o);
                S4b += __shfl_xor_sync(0xffffffffu, S4b, o);
            }

            // entropy: lane handles bin (lane&15)
            const int bn  = lane & 15;
            const int q   = bn & 3;
            const int idx = bn >> 2;
            const int sh  = (idx & 1) * 16;
            unsigned selA = (q == 0) ? ((idx < 2) ? ra0 : ra1)
                          : (q == 1) ? ((idx < 2) ? ra2 : ra3)
                          : (q == 2) ? ((idx < 2) ? ra4 : ra5)
                                     : ((idx < 2) ? ra6 : ra7);
            unsigned selB = (q == 0) ? ((idx < 2) ? rb0 : rb1)
                          : (q == 1) ? ((idx < 2) ? rb2 : rb3)
                          : (q == 2) ? ((idx < 2) ? rb4 : rb5)
                                     : ((idx < 2) ? rb6 : rb7);
            float p0 = (float)((selA >> sh) & 0xFFFFu) * invPr;
            float p1 = (float)((selB >> sh) & 0xFFFFu) * invPr;
            float ent0 = -p0 * __logf(p0 + 1e-9f);
            float ent1 = -p1 * __logf(p1 + 1e-9f);
            #pragma unroll
            for (int o = 1; o <= 8; o <<= 1) {
                ent0 += __shfl_xor_sync(0xffffffffu, ent0, o);
                ent1 += __shfl_xor_sync(0xffffffffu, ent1, o);
            }

            // moments -> stats
            float mu0 = S1a * inv288, mu1 = S1b * inv288;
            float r20 = S2a * inv288, r30 = S3a * inv288, r40 = S4a * inv288;
            float r21 = S2b * inv288, r31 = S3b * inv288, r41 = S4b * inv288;
            float mu20 = mu0 * mu0, mu21 = mu1 * mu1;
            float m20 = r20 - mu20, m21v = r21 - mu21;
            float m30 = r30 - mu0 * (3.0f * r20 - 2.0f * mu20);
            float m31 = r31 - mu1 * (3.0f * r21 - 2.0f * mu21);
            float m40 = r40 - mu0 * (4.0f * r30 - mu0 * (6.0f * r20 - 3.0f * mu20));
            float m41 = r41 - mu1 * (4.0f * r31 - mu1 * (6.0f * r21 - 3.0f * mu21));
            float sg0 = sqrtf(m20 + 1e-6f), sg1 = sqrtf(m21v + 1e-6f);
            float iq0 = 1.0f / (sg0 + 1e-6f), iq1 = 1.0f / (sg1 + 1e-6f);
            float iq20 = iq0 * iq0, iq21 = iq1 * iq1;
            float gm0 = m30 * iq20 * iq0, gm1 = m31 * iq21 * iq1;
            float kp0 = m40 * iq20 * iq20 - 3.0f, kp1 = m41 * iq21 * iq21 - 3.0f;

            // fc1 + relu
            float ss0[5] = {mu0, sg0, gm0, kp0, ent0};
            float ss1[5] = {mu1, sg1, gm1, kp1, ent1};
            float h00 = b1, h01 = b1b, h10 = b1, h11 = b1b;
            #pragma unroll
            for (int k = 0; k < 5; k++) {
                h00 += w1c[k]  * ss0[k];
                h01 += w1c2[k] * ss0[k];
                h10 += w1c[k]  * ss1[k];
                h11 += w1c2[k] * ss1[k];
            }
            sh_h[l0 * 64 + lane]      = fmaxf(h00, 0.f);
            sh_h[l0 * 64 + lane + 32] = fmaxf(h01, 0.f);
            sh_h[l1 * 64 + lane]      = fmaxf(h10, 0.f);
            sh_h[l1 * 64 + lane + 32] = fmaxf(h11, 0.f);
        }
    }
    __syncthreads();

    const int gr = lane >> 2, gc = lane & 3;
    const int r0 = warp * 16 + gr;              // valid for warp < 6

    // ---------------- phase 2: phi GEMM (+pbp column) on tensor cores + proj ----------
    if (warp < 6) {
        float d[8][4], d8[4];
        #pragma unroll
        for (int nt = 0; nt < 8; nt++)
            #pragma unroll
            for (int q2 = 0; q2 < 4; q2++) d[nt][q2] = 0.f;
        #pragma unroll
        for (int q2 = 0; q2 < 4; q2++) d8[q2] = 0.f;

        const int jc0 = 2 * gc, jc2 = 2 * gc + 8;
        for (int ks = 0; ks < 18; ks++) {
            const int jb = ks * 16;
            const int f0 = sh_f[jb + jc0], f1 = sh_f[jb + jc0 + 1];
            const int f2 = sh_f[jb + jc2], f3 = sh_f[jb + jc2 + 1];
            float v00 = sh_x[f0 + r0],     v01 = sh_x[f1 + r0];
            float v10 = sh_x[f0 + r0 + 8], v11 = sh_x[f1 + r0 + 8];
            float v20 = sh_x[f2 + r0],     v21 = sh_x[f3 + r0];
            float v30 = sh_x[f2 + r0 + 8], v31 = sh_x[f3 + r0 + 8];
            unsigned ah0 = bpack(v00, v01);
            unsigned ah1 = bpack(v10, v11);
            unsigned ah2 = bpack(v20, v21);
            unsigned ah3 = bpack(v30, v31);
            unsigned al0 = bpack(v00 - bf16val(v00), v01 - bf16val(v01));
            unsigned al1 = bpack(v10 - bf16val(v10), v11 - bf16val(v11));
            unsigned al2 = bpack(v20 - bf16val(v20), v21 - bf16val(v21));
            unsigned al3 = bpack(v30 - bf16val(v30), v31 - bf16val(v31));
            #pragma unroll
            for (int nt = 0; nt < 9; nt++) {
                const uint4 bf = __ldg(&g_Bf[(ks * 9 + nt) * 32 + lane]);
                float* dd = (nt < 8) ? d[nt] : d8;
                mma_bf16(dd, ah0, ah1, ah2, ah3, bf.x, bf.y);
                mma_bf16(dd, ah0, ah1, ah2, ah3, bf.z, bf.w);
                mma_bf16(dd, al0, al1, al2, al3, bf.x, bf.y);
            }
        }

        // proj: pr[l] = sum_h h[l][h]*t[h][l] + t_pb[l]
        float pr0 = (gc == 0) ? d8[0] : 0.f;
        float pr1 = (gc == 0) ? d8[2] : 0.f;
        #pragma unroll
        for (int nt = 0; nt < 8; nt++) {
            const float2 h0v = *(const float2*)(sh_h + r0 * 64 + nt * 8 + 2 * gc);
            const float2 h1v = *(const float2*)(sh_h + (r0 + 8) * 64 + nt * 8 + 2 * gc);
            pr0 += d[nt][0] * h0v.x + d[nt][1] * h0v.y;
            pr1 += d[nt][2] * h1v.x + d[nt][3] * h1v.y;
        }
        pr0 += __shfl_xor_sync(0xffffffffu, pr0, 1);
        pr0 += __shfl_xor_sync(0xffffffffu, pr0, 2);
        pr1 += __shfl_xor_sync(0xffffffffu, pr1, 1);
        pr1 += __shfl_xor_sync(0xffffffffu, pr1, 2);
        if (gc == 0) {
            sh_proj[r0]     = pr0;
            sh_proj[r0 + 8] = pr1;
        }
    }
    __syncthreads();

    // ---------------- phase 3: alpha GEMM + BN/SiLU, direct coalesced STG ----------
    if (warp < 6) {
        float d2[8][4];
        #pragma unroll
        for (int nt = 0; nt < 8; nt++)
            #pragma unroll
            for (int q2 = 0; q2 < 4; q2++) d2[nt][q2] = 0.f;

        #pragma unroll
        for (int ks = 0; ks < 4; ks++) {
            const float2* hr0 = (const float2*)(sh_h + r0 * 64 + ks * 16);
            const float2* hr1 = (const float2*)(sh_h + (r0 + 8) * 64 + ks * 16);
            float2 p00 = hr0[gc], p01 = hr0[gc + 4];
            float2 p10 = hr1[gc], p11 = hr1[gc + 4];
            unsigned ah0 = bpack(p00.x, p00.y);
            unsigned ah1 = bpack(p10.x, p10.y);
            unsigned ah2 = bpack(p01.x, p01.y);
            unsigned ah3 = bpack(p11.x, p11.y);
            unsigned al0 = bpack(p00.x - bf16val(p00.x), p00.y - bf16val(p00.y));
            unsigned al1 = bpack(p10.x - bf16val(p10.x), p10.y - bf16val(p10.y));
            unsigned al2 = bpack(p01.x - bf16val(p01.x), p01.y - bf16val(p01.y));
            unsigned al3 = bpack(p11.x - bf16val(p11.x), p11.y - bf16val(p11.y));
            #pragma unroll
            for (int nt = 0; nt < 8; nt++) {
                const uint4 bf = __ldg(&g_Af[(ks * 8 + nt) * 32 + lane]);
                mma_bf16(d2[nt], ah0, ah1, ah2, ah3, bf.x, bf.y);
                mma_bf16(d2[nt], ah0, ah1, ah2, ah3, bf.z, bf.w);
                mma_bf16(d2[nt], al0, al1, al2, al3, bf.x, bf.y);
            }
        }

        const float pj0 = sh_proj[r0];
        const float pj1 = sh_proj[r0 + 8];
        float* ob = out + (size_t)b * 64 * 9216 + y * 96;
        #pragma unroll
        for (int nt = 0; nt < 8; nt++) {
            const int c2 = nt * 8 + 2 * gc;
            const float4 bn0 = __ldg(&g_bn[c2]);       // {inv, mean, beta, alpha_b}
            const float4 bn1 = __ldg(&g_bn[c2 + 1]);
            float y00 = ((d2[nt][0] + bn0.w) * pj0 - bn0.y) * bn0.x + bn0.z;
            float y01 = ((d2[nt][1] + bn1.w) * pj0 - bn1.y) * bn1.x + bn1.z;
            float y10 = ((d2[nt][2] + bn0.w) * pj1 - bn0.y) * bn0.x + bn0.z;
            float y11 = ((d2[nt][3] + bn1.w) * pj1 - bn1.y) * bn1.x + bn1.z;
            // direct stores: per STG, 8 consecutive rows per gc-group -> 4 sectors/instr
            ob[(size_t)c2 * 9216 + r0]           = y00 / (1.0f + __expf(-y00));
            ob[(size_t)(c2 + 1) * 9216 + r0]     = y01 / (1.0f + __expf(-y01));
            ob[(size_t)c2 * 9216 + r0 + 8]       = y10 / (1.0f + __expf(-y10));
            ob[(size_t)(c2 + 1) * 9216 + r0 + 8] = y11 / (1.0f + __expf(-y11));
        }
    }
}

extern "C" void kernel_launch(void* const* d_in, const int* in_sizes, int n_in,
                              void* d_out, int out_size) {
    int ix = -1, ifc1w = -1, iaw = -1, ipw = -1, ipb = -1;
    int idx64[8]; int n64 = 0;
    for (int i = 0; i < n_in; i++) {
        switch (in_sizes[i]) {
            case 1179648: ix    = i; break;
            case 18432:   ipw   = i; break;
            case 4096:    iaw   = i; break;
            case 320:     ifc1w = i; break;
            case 288:     ipb   = i; break;
            case 64:      if (n64 < 8) idx64[n64++] = i; break;
            default: break;
        }
    }
    int ifc1b, iab, ibg, ibb, ibm, ibv;
    if (ix < 0 || ipw < 0 || iaw < 0 || ifc1w < 0 || ipb < 0 || n64 < 6) {
        ix = 0; ifc1w = 1; ifc1b = 2; iaw = 3; iab = 4; ipw = 5; ipb = 6;
        ibg = 7; ibb = 8; ibm = 9; ibv = 10;
    } else if (ix == 0) {
        ifc1b = idx64[0]; iab = idx64[1]; ibg = idx64[2];
        ibb   = idx64[3]; ibm = idx64[4]; ibv = idx64[5];
    } else {
        iab   = idx64[0]; ibb = idx64[1]; ibg = idx64[2];
        ibm   = idx64[3]; ibv = idx64[4]; ifc1b = idx64[5];
    }

    const float* x        = (const float*)d_in[ix];
    const float* fc1_w    = (const float*)d_in[ifc1w];
    const float* fc1_b    = (const float*)d_in[ifc1b];
    const float* alpha_w  = (const float*)d_in[iaw];
    const float* alpha_b  = (const float*)d_in[iab];
    const float* phi_w    = (const float*)d_in[ipw];
    const float* phi_b    = (const float*)d_in[ipb];
    const float* bn_gamma = (const float*)d_in[ibg];
    const float* bn_beta  = (const float*)d_in[ibb];
    const float* bn_mean  = (const float*)d_in[ibm];
    const float* bn_var   = (const float*)d_in[ibv];
    float* out = (float*)d_out;

    cudaFuncSetAttribute(sac_kernel, cudaFuncAttributeMaxDynamicSharedMemorySize, SMEM_BYTES);

    prep_kernel<<<21, 256>>>(alpha_w, phi_w, phi_b, alpha_b,
                             bn_gamma, bn_beta, bn_mean, bn_var);
    dim3 grid(96, 4);
    sac_kernel<<<grid, TPB, SMEM_BYTES>>>(x, fc1_w, fc1_b, out);
}